// round 1
// baseline (speedup 1.0000x reference)
#include <cuda_runtime.h>
#include <cuda_bf16.h>
#include <math.h>

// ---------------------------------------------------------------------------
// Problem constants
// ---------------------------------------------------------------------------
#define TOKENS   4096           // B*T = 2*2048
#define TSEQ     2048
#define DMODEL   1024
#define NHEADS   16
#define DHEAD    64
#define DFF      4096
#define WINDOW   256

// ---------------------------------------------------------------------------
// Scratch (device globals; no runtime allocation allowed)
// ---------------------------------------------------------------------------
__device__ float g_xn  [(size_t)TOKENS * DMODEL];      // rmsnorm1 output
__device__ float g_qkv [(size_t)TOKENS * 3 * DMODEL];  // qkv projections
__device__ float g_gate[(size_t)TOKENS * DMODEL];      // sigmoid(x@gate_w.T)
__device__ float g_attn[(size_t)TOKENS * DMODEL];      // gated attention out
__device__ float g_hn  [(size_t)TOKENS * DMODEL];      // rmsnorm2 output
__device__ float g_g   [(size_t)TOKENS * DFF];         // silu(h@wg.T)
__device__ float g_u   [(size_t)TOKENS * DFF];         // silu(g)*u

// ---------------------------------------------------------------------------
// RMSNorm: one block per row of 1024 floats
// ---------------------------------------------------------------------------
__global__ void __launch_bounds__(256) rmsnorm_kernel(
    const float* __restrict__ x, const float* __restrict__ w,
    float* __restrict__ out)
{
    __shared__ float warp_sums[8];
    int row = blockIdx.x;
    int tid = threadIdx.x;
    const float4* x4 = (const float4*)(x + (size_t)row * DMODEL);
    const float4* w4 = (const float4*)w;
    float4 xv = x4[tid];
    float ss = xv.x * xv.x + xv.y * xv.y + xv.z * xv.z + xv.w * xv.w;
    // warp reduce
    #pragma unroll
    for (int o = 16; o > 0; o >>= 1) ss += __shfl_xor_sync(0xffffffffu, ss, o);
    if ((tid & 31) == 0) warp_sums[tid >> 5] = ss;
    __syncthreads();
    if (tid < 8) {
        float v = warp_sums[tid];
        #pragma unroll
        for (int o = 4; o > 0; o >>= 1) v += __shfl_xor_sync(0xffu, v, o);
        if (tid == 0) warp_sums[0] = v;
    }
    __syncthreads();
    float scale = rsqrtf(warp_sums[0] * (1.0f / DMODEL) + 1e-6f);
    float4 wv = w4[tid];
    float4 r;
    r.x = xv.x * scale * wv.x;
    r.y = xv.y * scale * wv.y;
    r.z = xv.z * scale * wv.z;
    r.w = xv.w * scale * wv.w;
    ((float4*)(out + (size_t)row * DMODEL))[tid] = r;
}

// ---------------------------------------------------------------------------
// SGEMM (NT): C[M,N] = A[M,K] * B[N,K]^T, all row-major, K-major operands.
// 128x128 block tile, BK=16, 256 threads, 8x8 per-thread micro-tile.
// All problem dims are multiples of the tiles -> no bounds checks.
// Epilogues:
//   0 = none
//   1 = sigmoid(v)
//   2 = silu(v)
//   3 = v * aux[m*N+n]
//   4 = v + aux[m*N+n]
// ---------------------------------------------------------------------------
#define BM 128
#define BN 128
#define BK 16

__device__ __forceinline__ float sigmoid_f(float x) {
    return 1.0f / (1.0f + __expf(-x));
}

template <int EPI>
__global__ void __launch_bounds__(256) sgemm_nt(
    const float* __restrict__ A, const float* __restrict__ B,
    float* __restrict__ C, const float* __restrict__ aux,
    int M, int N, int K)
{
    __shared__ float As[BK][BM];
    __shared__ float Bs[BK][BN];

    int tid = threadIdx.x;
    int m0 = blockIdx.y * BM;
    int n0 = blockIdx.x * BN;

    int lm = tid & 127;     // row within tile (m for A, n for B)
    int lk = tid >> 7;      // 0..1 -> base k-group

    const float* Ag = A + (size_t)(m0 + lm) * K;
    const float* Bg = B + (size_t)(n0 + lm) * K;

    float acc[8][8];
    #pragma unroll
    for (int i = 0; i < 8; i++)
        #pragma unroll
        for (int j = 0; j < 8; j++) acc[i][j] = 0.0f;

    int ty = tid >> 4;   // 0..15 -> m micro-tile
    int tx = tid & 15;   // 0..15 -> n micro-tile

    for (int k0 = 0; k0 < K; k0 += BK) {
        #pragma unroll
        for (int it = 0; it < 2; ++it) {
            int kg = lk + it * 2;  // 0..3 (k-group of 4)
            float4 a = *(const float4*)(Ag + k0 + kg * 4);
            float4 b = *(const float4*)(Bg + k0 + kg * 4);
            As[kg * 4 + 0][lm] = a.x;
            As[kg * 4 + 1][lm] = a.y;
            As[kg * 4 + 2][lm] = a.z;
            As[kg * 4 + 3][lm] = a.w;
            Bs[kg * 4 + 0][lm] = b.x;
            Bs[kg * 4 + 1][lm] = b.y;
            Bs[kg * 4 + 2][lm] = b.z;
            Bs[kg * 4 + 3][lm] = b.w;
        }
        __syncthreads();

        #pragma unroll
        for (int kk = 0; kk < BK; ++kk) {
            float ra[8], rb[8];
            *(float4*)(ra + 0) = *(const float4*)&As[kk][ty * 8 + 0];
            *(float4*)(ra + 4) = *(const float4*)&As[kk][ty * 8 + 4];
            *(float4*)(rb + 0) = *(const float4*)&Bs[kk][tx * 8 + 0];
            *(float4*)(rb + 4) = *(const float4*)&Bs[kk][tx * 8 + 4];
            #pragma unroll
            for (int i = 0; i < 8; i++)
                #pragma unroll
                for (int j = 0; j < 8; j++)
                    acc[i][j] += ra[i] * rb[j];
        }
        __syncthreads();
    }

    // Epilogue
    #pragma unroll
    for (int i = 0; i < 8; i++) {
        int m = m0 + ty * 8 + i;
        size_t base = (size_t)m * N + n0 + tx * 8;
        #pragma unroll
        for (int j = 0; j < 8; j += 4) {
            float v[4] = {acc[i][j], acc[i][j + 1], acc[i][j + 2], acc[i][j + 3]};
            if (EPI == 1) {
                #pragma unroll
                for (int t = 0; t < 4; t++) v[t] = sigmoid_f(v[t]);
            } else if (EPI == 2) {
                #pragma unroll
                for (int t = 0; t < 4; t++) v[t] = v[t] * sigmoid_f(v[t]);
            } else if (EPI == 3) {
                float4 a4 = *(const float4*)(aux + base + j);
                v[0] *= a4.x; v[1] *= a4.y; v[2] *= a4.z; v[3] *= a4.w;
            } else if (EPI == 4) {
                float4 a4 = *(const float4*)(aux + base + j);
                v[0] += a4.x; v[1] += a4.y; v[2] += a4.z; v[3] += a4.w;
            }
            float4 o4 = make_float4(v[0], v[1], v[2], v[3]);
            *(float4*)(C + base + j) = o4;
        }
    }
}

// ---------------------------------------------------------------------------
// Sliding-window causal attention with fused gate.
// Block: 64 q-rows of one (batch, head); 128 threads, 2 per q-row
// (each owns half of D_HEAD). K/V streamed in 64-key smem tiles.
// Online softmax with lazy rescale. Output multiplied by sigmoid gate.
// ---------------------------------------------------------------------------
__global__ void __launch_bounds__(128) attn_kernel(
    const float* __restrict__ qkv, const float* __restrict__ gate,
    float* __restrict__ out)
{
    __shared__ float4 Ks[64 * 16];   // [key][c4], 16 float4 = 64 floats per key
    __shared__ float4 Vs[64 * 16];

    int tid  = threadIdx.x;
    int row  = tid >> 1;
    int half = tid & 1;
    int b = blockIdx.y >> 4;
    int h = blockIdx.y & 15;
    int q0 = blockIdx.x * 64;
    int qi = q0 + row;
    size_t tq = (size_t)b * TSEQ + qi;

    const float4* qp = (const float4*)(qkv + tq * (3 * DMODEL) + h * DHEAD + half * 32);
    float4 qv[8];
    #pragma unroll
    for (int i = 0; i < 8; i++) qv[i] = qp[i];

    float4 o[8];
    #pragma unroll
    for (int i = 0; i < 8; i++) o[i] = make_float4(0.f, 0.f, 0.f, 0.f);
    float m = -1e30f, l = 0.0f;

    int s_lo = q0 - WINDOW;
    if (s_lo < 0) s_lo = 0;

    for (int s = s_lo; s <= q0; s += 64) {
        // cooperative K/V tile load (coalesced: 16 consecutive float4 per key)
        for (int i = tid; i < 1024; i += 128) {
            int key = i >> 4;
            int c   = i & 15;
            size_t base = ((size_t)b * TSEQ + s + key) * (3 * DMODEL) + h * DHEAD + c * 4;
            Ks[i] = *(const float4*)(qkv + base + DMODEL);
            Vs[i] = *(const float4*)(qkv + base + 2 * DMODEL);
        }
        __syncthreads();

        for (int j = 0; j < 64; ++j) {
            int k = s + j;
            int dist = qi - k;
            float p = 0.0f;
            const float4* kp = &Ks[j * 16 + half * 8];
            #pragma unroll
            for (int i = 0; i < 8; i++) {
                float4 kv = kp[i];
                p += qv[i].x * kv.x + qv[i].y * kv.y + qv[i].z * kv.z + qv[i].w * kv.w;
            }
            p += __shfl_xor_sync(0xffffffffu, p, 1);  // combine the two halves
            if (dist >= 0 && dist < WINDOW) {
                float sc = p * 0.125f;  // 1/sqrt(64)
                if (sc > m) {
                    float cfac = __expf(m - sc);
                    l *= cfac;
                    #pragma unroll
                    for (int i = 0; i < 8; i++) {
                        o[i].x *= cfac; o[i].y *= cfac;
                        o[i].z *= cfac; o[i].w *= cfac;
                    }
                    m = sc;
                }
                float pe = __expf(sc - m);
                l += pe;
                const float4* vp = &Vs[j * 16 + half * 8];
                #pragma unroll
                for (int i = 0; i < 8; i++) {
                    float4 vv = vp[i];
                    o[i].x += pe * vv.x; o[i].y += pe * vv.y;
                    o[i].z += pe * vv.z; o[i].w += pe * vv.w;
                }
            }
        }
        __syncthreads();
    }

    float inv = 1.0f / l;
    const float4* gp = (const float4*)(gate + tq * DMODEL + h * DHEAD + half * 32);
    float4* op = (float4*)(out + tq * DMODEL + h * DHEAD + half * 32);
    #pragma unroll
    for (int i = 0; i < 8; i++) {
        float4 g4 = gp[i];
        float4 v;
        v.x = o[i].x * inv * g4.x;
        v.y = o[i].y * inv * g4.y;
        v.z = o[i].z * inv * g4.z;
        v.w = o[i].w * inv * g4.w;
        op[i] = v;
    }
}

// ---------------------------------------------------------------------------
// Launch
// ---------------------------------------------------------------------------
extern "C" void kernel_launch(void* const* d_in, const int* in_sizes, int n_in,
                              void* d_out, int out_size)
{
    const float* x      = (const float*)d_in[0];
    const float* ln1_w  = (const float*)d_in[1];
    const float* qkv_w  = (const float*)d_in[2];
    const float* gate_w = (const float*)d_in[3];
    const float* out_w  = (const float*)d_in[4];
    const float* ln2_w  = (const float*)d_in[5];
    const float* wg     = (const float*)d_in[6];
    const float* wu     = (const float*)d_in[7];
    const float* wo     = (const float*)d_in[8];
    float* out = (float*)d_out;

    float *xn, *qkvb, *gateb, *attnb, *hn, *gb, *ub;
    cudaGetSymbolAddress((void**)&xn,    g_xn);
    cudaGetSymbolAddress((void**)&qkvb,  g_qkv);
    cudaGetSymbolAddress((void**)&gateb, g_gate);
    cudaGetSymbolAddress((void**)&attnb, g_attn);
    cudaGetSymbolAddress((void**)&hn,    g_hn);
    cudaGetSymbolAddress((void**)&gb,    g_g);
    cudaGetSymbolAddress((void**)&ub,    g_u);

    // 1. xn = rmsnorm(x, ln1_w)
    rmsnorm_kernel<<<TOKENS, 256>>>(x, ln1_w, xn);

    // 2. qkv = xn @ qkv_w^T          [4096, 3072]
    sgemm_nt<0><<<dim3(3 * DMODEL / BN, TOKENS / BM), 256>>>(
        xn, qkv_w, qkvb, nullptr, TOKENS, 3 * DMODEL, DMODEL);

    // 3. gate = sigmoid(xn @ gate_w^T)   [4096, 1024]
    sgemm_nt<1><<<dim3(DMODEL / BN, TOKENS / BM), 256>>>(
        xn, gate_w, gateb, nullptr, TOKENS, DMODEL, DMODEL);

    // 4. attn = sliding-window attention, gated   [4096, 1024]
    attn_kernel<<<dim3(TSEQ / 64, 2 * NHEADS), 128>>>(qkvb, gateb, attnb);

    // 5. x1 = x + attn @ out_w^T  -> d_out
    sgemm_nt<4><<<dim3(DMODEL / BN, TOKENS / BM), 256>>>(
        attnb, out_w, out, x, TOKENS, DMODEL, DMODEL);

    // 6. hn = rmsnorm(x1, ln2_w)
    rmsnorm_kernel<<<TOKENS, 256>>>(out, ln2_w, hn);

    // 7. g = silu(hn @ wg^T)   [4096, 4096]
    sgemm_nt<2><<<dim3(DFF / BN, TOKENS / BM), 256>>>(
        hn, wg, gb, nullptr, TOKENS, DFF, DMODEL);

    // 8. act = g * (hn @ wu^T)   [4096, 4096]
    sgemm_nt<3><<<dim3(DFF / BN, TOKENS / BM), 256>>>(
        hn, wu, ub, gb, TOKENS, DFF, DMODEL);

    // 9. out = x1 + act @ wo^T   (in-place residual add on d_out)
    sgemm_nt<4><<<dim3(DMODEL / BN, TOKENS / BM), 256>>>(
        ub, wo, out, out, TOKENS, DMODEL, DFF);
}

// round 3
// speedup vs baseline: 2.0762x; 2.0762x over previous
#include <cuda_runtime.h>
#include <cuda_bf16.h>
#include <math.h>
#include <cstdint>

// ---------------------------------------------------------------------------
// Problem constants
// ---------------------------------------------------------------------------
#define TOKENS   4096           // B*T = 2*2048
#define TSEQ     2048
#define DMODEL   1024
#define NHEADS   16
#define DHEAD    64
#define DFF      4096
#define WINDOW   256

// ---------------------------------------------------------------------------
// Scratch (device globals; no runtime allocation allowed)
// ---------------------------------------------------------------------------
__device__ float g_xn  [(size_t)TOKENS * DMODEL];      // rmsnorm1 output
__device__ float g_qkv [(size_t)TOKENS * 3 * DMODEL];  // qkv projections
__device__ float g_gate[(size_t)TOKENS * DMODEL];      // sigmoid(x@gate_w.T)
__device__ float g_attn[(size_t)TOKENS * DMODEL];      // gated attention out
__device__ float g_hn  [(size_t)TOKENS * DMODEL];      // rmsnorm2 output
__device__ float g_g   [(size_t)TOKENS * DFF];         // silu(h@wg.T)
__device__ float g_u   [(size_t)TOKENS * DFF];         // silu*u

// ---------------------------------------------------------------------------
// Helpers
// ---------------------------------------------------------------------------
__device__ __forceinline__ float sigmoid_f(float x) {
    return 1.0f / (1.0f + __expf(-x));
}

__device__ __forceinline__ uint32_t f2tf32(float x) {
    uint32_t r;
    asm("cvt.rna.tf32.f32 %0, %1;" : "=r"(r) : "f"(x));
    return r;
}

__device__ __forceinline__ void mma_tf32(float* d, const uint32_t* a, const uint32_t* b) {
    asm volatile(
        "mma.sync.aligned.m16n8k8.row.col.f32.tf32.tf32.f32 "
        "{%0,%1,%2,%3}, {%4,%5,%6,%7}, {%8,%9}, {%0,%1,%2,%3};"
        : "+f"(d[0]), "+f"(d[1]), "+f"(d[2]), "+f"(d[3])
        : "r"(a[0]), "r"(a[1]), "r"(a[2]), "r"(a[3]), "r"(b[0]), "r"(b[1]));
}

// ---------------------------------------------------------------------------
// RMSNorm: one block per row of 1024 floats
// ---------------------------------------------------------------------------
__global__ void __launch_bounds__(256) rmsnorm_kernel(
    const float* __restrict__ x, const float* __restrict__ w,
    float* __restrict__ out)
{
    __shared__ float warp_sums[8];
    int row = blockIdx.x;
    int tid = threadIdx.x;
    const float4* x4 = (const float4*)(x + (size_t)row * DMODEL);
    const float4* w4 = (const float4*)w;
    float4 xv = x4[tid];
    float ss = xv.x * xv.x + xv.y * xv.y + xv.z * xv.z + xv.w * xv.w;
    #pragma unroll
    for (int o = 16; o > 0; o >>= 1) ss += __shfl_xor_sync(0xffffffffu, ss, o);
    if ((tid & 31) == 0) warp_sums[tid >> 5] = ss;
    __syncthreads();
    if (tid < 8) {
        float v = warp_sums[tid];
        #pragma unroll
        for (int o = 4; o > 0; o >>= 1) v += __shfl_xor_sync(0xffu, v, o);
        if (tid == 0) warp_sums[0] = v;
    }
    __syncthreads();
    float scale = rsqrtf(warp_sums[0] * (1.0f / DMODEL) + 1e-6f);
    float4 wv = w4[tid];
    float4 r;
    r.x = xv.x * scale * wv.x;
    r.y = xv.y * scale * wv.y;
    r.z = xv.z * scale * wv.z;
    r.w = xv.w * scale * wv.w;
    ((float4*)(out + (size_t)row * DMODEL))[tid] = r;
}

// ---------------------------------------------------------------------------
// Tensor-core tf32 GEMM (NT): C[M,N] = A[M,K] * B[N,K]^T via mma.sync m16n8k8.
//
// CTA tile 128x128, BK=16, 256 threads (8 warps as 2x4 -> warp tile 64x32).
// SMEM layout: per 16-k chunk, logical k stored at slot (k&3)*4 + (k>>2), so
// each lane's fragment k-values {t, t+4, t+8, t+12} form one LDS.128.
// Row stride = 20 floats (80B): 20*r mod 32 is distinct for r=0..7, making
// both scattered STS.32 and LDS.128 bank-conflict-free.
//
// EPI: 0=none 1=sigmoid 2=silu 3=mul aux 4=add aux
// ---------------------------------------------------------------------------
#define ROWB 80      // bytes per smem row (20 floats)

template <int EPI>
__global__ void __launch_bounds__(256) gemm_mma(
    const float* __restrict__ A, const float* __restrict__ B,
    float* __restrict__ C, const float* __restrict__ aux,
    int M, int N, int K)
{
    __shared__ __align__(16) unsigned char sm[2][2][128 * ROWB];  // [buf][A/B]

    int tid  = threadIdx.x;
    int warp = tid >> 5;
    int lane = tid & 31;
    int g = lane >> 2;
    int t = lane & 3;
    int m0 = blockIdx.y * 128;
    int n0 = blockIdx.x * 128;
    int wm = (warp & 1) * 64;      // warp m offset
    int wn = (warp >> 1) * 32;     // warp n offset

    const float* Ab = A + (size_t)m0 * K;
    const float* Bb = B + (size_t)n0 * K;

    // loader mapping: slot s in [0,512): row = s>>2, q = s&3 (quad of 4 k)
    int lrow0 = tid >> 2,            lq0 = tid & 3;
    int lrow1 = (tid + 256) >> 2,    lq1 = tid & 3;  // +256 keeps q, row += 64

    float acc[4][4][4];
    #pragma unroll
    for (int f = 0; f < 4; f++)
        #pragma unroll
        for (int n = 0; n < 4; n++)
            #pragma unroll
            for (int i = 0; i < 4; i++) acc[f][n][i] = 0.0f;

    // ---- stage chunk 0 ----
    {
        float4 a0 = *(const float4*)(Ab + (size_t)lrow0 * K + lq0 * 4);
        float4 a1 = *(const float4*)(Ab + (size_t)lrow1 * K + lq1 * 4);
        float4 b0 = *(const float4*)(Bb + (size_t)lrow0 * K + lq0 * 4);
        float4 b1 = *(const float4*)(Bb + (size_t)lrow1 * K + lq1 * 4);
        unsigned char* pa0 = &sm[0][0][lrow0 * ROWB + lq0 * 4];
        unsigned char* pa1 = &sm[0][0][lrow1 * ROWB + lq1 * 4];
        unsigned char* pb0 = &sm[0][1][lrow0 * ROWB + lq0 * 4];
        unsigned char* pb1 = &sm[0][1][lrow1 * ROWB + lq1 * 4];
        *(uint32_t*)(pa0 +  0) = f2tf32(a0.x);
        *(uint32_t*)(pa0 + 16) = f2tf32(a0.y);
        *(uint32_t*)(pa0 + 32) = f2tf32(a0.z);
        *(uint32_t*)(pa0 + 48) = f2tf32(a0.w);
        *(uint32_t*)(pa1 +  0) = f2tf32(a1.x);
        *(uint32_t*)(pa1 + 16) = f2tf32(a1.y);
        *(uint32_t*)(pa1 + 32) = f2tf32(a1.z);
        *(uint32_t*)(pa1 + 48) = f2tf32(a1.w);
        *(uint32_t*)(pb0 +  0) = f2tf32(b0.x);
        *(uint32_t*)(pb0 + 16) = f2tf32(b0.y);
        *(uint32_t*)(pb0 + 32) = f2tf32(b0.z);
        *(uint32_t*)(pb0 + 48) = f2tf32(b0.w);
        *(uint32_t*)(pb1 +  0) = f2tf32(b1.x);
        *(uint32_t*)(pb1 + 16) = f2tf32(b1.y);
        *(uint32_t*)(pb1 + 32) = f2tf32(b1.z);
        *(uint32_t*)(pb1 + 48) = f2tf32(b1.w);
    }
    __syncthreads();

    int nch = K >> 4;

    for (int c = 0; c < nch; c++) {
        int buf = c & 1;
        int have = (c + 1 < nch);
        float4 ra0, ra1, rb0, rb1;
        if (have) {
            int k0 = (c + 1) << 4;
            ra0 = *(const float4*)(Ab + (size_t)lrow0 * K + k0 + lq0 * 4);
            ra1 = *(const float4*)(Ab + (size_t)lrow1 * K + k0 + lq1 * 4);
            rb0 = *(const float4*)(Bb + (size_t)lrow0 * K + k0 + lq0 * 4);
            rb1 = *(const float4*)(Bb + (size_t)lrow1 * K + k0 + lq1 * 4);
        }

        // ---- compute on buf ----
        {
            const unsigned char* As = sm[buf][0];
            const unsigned char* Bs = sm[buf][1];
            uint32_t af[4][2][4];   // [mfrag][half(row +8)][k-slot]
            uint32_t bf[4][4];      // [nfrag][k-slot]
            #pragma unroll
            for (int f = 0; f < 4; f++) {
                #pragma unroll
                for (int h = 0; h < 2; h++) {
                    uint4 v = *(const uint4*)(As + (wm + f * 16 + h * 8 + g) * ROWB + t * 16);
                    af[f][h][0] = v.x; af[f][h][1] = v.y;
                    af[f][h][2] = v.z; af[f][h][3] = v.w;
                }
            }
            #pragma unroll
            for (int n = 0; n < 4; n++) {
                uint4 v = *(const uint4*)(Bs + (wn + n * 8 + g) * ROWB + t * 16);
                bf[n][0] = v.x; bf[n][1] = v.y; bf[n][2] = v.z; bf[n][3] = v.w;
            }
            #pragma unroll
            for (int f = 0; f < 4; f++) {
                #pragma unroll
                for (int n = 0; n < 4; n++) {
                    // k-step 0: slots 0 (k=t) and 1 (k=t+4)
                    uint32_t a0[4] = { af[f][0][0], af[f][1][0], af[f][0][1], af[f][1][1] };
                    uint32_t b0[2] = { bf[n][0], bf[n][1] };
                    mma_tf32(acc[f][n], a0, b0);
                    // k-step 1: slots 2 (k=t+8) and 3 (k=t+12)
                    uint32_t a1[4] = { af[f][0][2], af[f][1][2], af[f][0][3], af[f][1][3] };
                    uint32_t b1[2] = { bf[n][2], bf[n][3] };
                    mma_tf32(acc[f][n], a1, b1);
                }
            }
        }

        if (have) {
            int nb = buf ^ 1;
            unsigned char* pa0 = &sm[nb][0][lrow0 * ROWB + lq0 * 4];
            unsigned char* pa1 = &sm[nb][0][lrow1 * ROWB + lq1 * 4];
            unsigned char* pb0 = &sm[nb][1][lrow0 * ROWB + lq0 * 4];
            unsigned char* pb1 = &sm[nb][1][lrow1 * ROWB + lq1 * 4];
            *(uint32_t*)(pa0 +  0) = f2tf32(ra0.x);
            *(uint32_t*)(pa0 + 16) = f2tf32(ra0.y);
            *(uint32_t*)(pa0 + 32) = f2tf32(ra0.z);
            *(uint32_t*)(pa0 + 48) = f2tf32(ra0.w);
            *(uint32_t*)(pa1 +  0) = f2tf32(ra1.x);
            *(uint32_t*)(pa1 + 16) = f2tf32(ra1.y);
            *(uint32_t*)(pa1 + 32) = f2tf32(ra1.z);
            *(uint32_t*)(pa1 + 48) = f2tf32(ra1.w);
            *(uint32_t*)(pb0 +  0) = f2tf32(rb0.x);
            *(uint32_t*)(pb0 + 16) = f2tf32(rb0.y);
            *(uint32_t*)(pb0 + 32) = f2tf32(rb0.z);
            *(uint32_t*)(pb0 + 48) = f2tf32(rb0.w);
            *(uint32_t*)(pb1 +  0) = f2tf32(rb1.x);
            *(uint32_t*)(pb1 + 16) = f2tf32(rb1.y);
            *(uint32_t*)(pb1 + 32) = f2tf32(rb1.z);
            *(uint32_t*)(pb1 + 48) = f2tf32(rb1.w);
        }
        __syncthreads();
    }

    // ---- epilogue ----
    #pragma unroll
    for (int f = 0; f < 4; f++) {
        int r0 = m0 + wm + f * 16 + g;
        #pragma unroll
        for (int n = 0; n < 4; n++) {
            int cc = n0 + wn + n * 8 + 2 * t;
            float v0 = acc[f][n][0], v1 = acc[f][n][1];
            float v2 = acc[f][n][2], v3 = acc[f][n][3];
            size_t i0 = (size_t)r0 * N + cc;
            size_t i1 = (size_t)(r0 + 8) * N + cc;
            if (EPI == 1) {
                v0 = sigmoid_f(v0); v1 = sigmoid_f(v1);
                v2 = sigmoid_f(v2); v3 = sigmoid_f(v3);
            } else if (EPI == 2) {
                v0 *= sigmoid_f(v0); v1 *= sigmoid_f(v1);
                v2 *= sigmoid_f(v2); v3 *= sigmoid_f(v3);
            } else if (EPI == 3) {
                float2 x0 = *(const float2*)(aux + i0);
                float2 x1 = *(const float2*)(aux + i1);
                v0 *= x0.x; v1 *= x0.y; v2 *= x1.x; v3 *= x1.y;
            } else if (EPI == 4) {
                float2 x0 = *(const float2*)(aux + i0);
                float2 x1 = *(const float2*)(aux + i1);
                v0 += x0.x; v1 += x0.y; v2 += x1.x; v3 += x1.y;
            }
            *(float2*)(C + i0) = make_float2(v0, v1);
            *(float2*)(C + i1) = make_float2(v2, v3);
        }
    }
}

// ---------------------------------------------------------------------------
// Sliding-window causal attention with fused gate (unchanged from R1).
// ---------------------------------------------------------------------------
__global__ void __launch_bounds__(128) attn_kernel(
    const float* __restrict__ qkv, const float* __restrict__ gate,
    float* __restrict__ out)
{
    __shared__ float4 Ks[64 * 16];
    __shared__ float4 Vs[64 * 16];

    int tid  = threadIdx.x;
    int row  = tid >> 1;
    int half = tid & 1;
    int b = blockIdx.y >> 4;
    int h = blockIdx.y & 15;
    int q0 = blockIdx.x * 64;
    int qi = q0 + row;
    size_t tq = (size_t)b * TSEQ + qi;

    const float4* qp = (const float4*)(qkv + tq * (3 * DMODEL) + h * DHEAD + half * 32);
    float4 qv[8];
    #pragma unroll
    for (int i = 0; i < 8; i++) qv[i] = qp[i];

    float4 o[8];
    #pragma unroll
    for (int i = 0; i < 8; i++) o[i] = make_float4(0.f, 0.f, 0.f, 0.f);
    float m = -1e30f, l = 0.0f;

    int s_lo = q0 - WINDOW;
    if (s_lo < 0) s_lo = 0;

    for (int s = s_lo; s <= q0; s += 64) {
        for (int i = tid; i < 1024; i += 128) {
            int key = i >> 4;
            int c   = i & 15;
            size_t base = ((size_t)b * TSEQ + s + key) * (3 * DMODEL) + h * DHEAD + c * 4;
            Ks[i] = *(const float4*)(qkv + base + DMODEL);
            Vs[i] = *(const float4*)(qkv + base + 2 * DMODEL);
        }
        __syncthreads();

        for (int j = 0; j < 64; ++j) {
            int k = s + j;
            int dist = qi - k;
            float p = 0.0f;
            const float4* kp = &Ks[j * 16 + half * 8];
            #pragma unroll
            for (int i = 0; i < 8; i++) {
                float4 kv = kp[i];
                p += qv[i].x * kv.x + qv[i].y * kv.y + qv[i].z * kv.z + qv[i].w * kv.w;
            }
            p += __shfl_xor_sync(0xffffffffu, p, 1);
            if (dist >= 0 && dist < WINDOW) {
                float sc = p * 0.125f;
                if (sc > m) {
                    float cfac = __expf(m - sc);
                    l *= cfac;
                    #pragma unroll
                    for (int i = 0; i < 8; i++) {
                        o[i].x *= cfac; o[i].y *= cfac;
                        o[i].z *= cfac; o[i].w *= cfac;
                    }
                    m = sc;
                }
                float pe = __expf(sc - m);
                l += pe;
                const float4* vp = &Vs[j * 16 + half * 8];
                #pragma unroll
                for (int i = 0; i < 8; i++) {
                    float4 vv = vp[i];
                    o[i].x += pe * vv.x; o[i].y += pe * vv.y;
                    o[i].z += pe * vv.z; o[i].w += pe * vv.w;
                }
            }
        }
        __syncthreads();
    }

    float inv = 1.0f / l;
    const float4* gp = (const float4*)(gate + tq * DMODEL + h * DHEAD + half * 32);
    float4* op = (float4*)(out + tq * DMODEL + h * DHEAD + half * 32);
    #pragma unroll
    for (int i = 0; i < 8; i++) {
        float4 g4 = gp[i];
        float4 v;
        v.x = o[i].x * inv * g4.x;
        v.y = o[i].y * inv * g4.y;
        v.z = o[i].z * inv * g4.z;
        v.w = o[i].w * inv * g4.w;
        op[i] = v;
    }
}

// ---------------------------------------------------------------------------
// Launch
// ---------------------------------------------------------------------------
extern "C" void kernel_launch(void* const* d_in, const int* in_sizes, int n_in,
                              void* d_out, int out_size)
{
    const float* x      = (const float*)d_in[0];
    const float* ln1_w  = (const float*)d_in[1];
    const float* qkv_w  = (const float*)d_in[2];
    const float* gate_w = (const float*)d_in[3];
    const float* out_w  = (const float*)d_in[4];
    const float* ln2_w  = (const float*)d_in[5];
    const float* wg     = (const float*)d_in[6];
    const float* wu     = (const float*)d_in[7];
    const float* wo     = (const float*)d_in[8];
    float* out = (float*)d_out;

    float *xn, *qkvb, *gateb, *attnb, *hn, *gb, *ub;
    cudaGetSymbolAddress((void**)&xn,    g_xn);
    cudaGetSymbolAddress((void**)&qkvb,  g_qkv);
    cudaGetSymbolAddress((void**)&gateb, g_gate);
    cudaGetSymbolAddress((void**)&attnb, g_attn);
    cudaGetSymbolAddress((void**)&hn,    g_hn);
    cudaGetSymbolAddress((void**)&gb,    g_g);
    cudaGetSymbolAddress((void**)&ub,    g_u);

    // 1. xn = rmsnorm(x, ln1_w)
    rmsnorm_kernel<<<TOKENS, 256>>>(x, ln1_w, xn);

    // 2. qkv = xn @ qkv_w^T          [4096, 3072]
    gemm_mma<0><<<dim3(3 * DMODEL / 128, TOKENS / 128), 256>>>(
        xn, qkv_w, qkvb, nullptr, TOKENS, 3 * DMODEL, DMODEL);

    // 3. gate = sigmoid(xn @ gate_w^T)   [4096, 1024]
    gemm_mma<1><<<dim3(DMODEL / 128, TOKENS / 128), 256>>>(
        xn, gate_w, gateb, nullptr, TOKENS, DMODEL, DMODEL);

    // 4. attn = sliding-window attention, gated   [4096, 1024]
    attn_kernel<<<dim3(TSEQ / 64, 2 * NHEADS), 128>>>(qkvb, gateb, attnb);

    // 5. x1 = x + attn @ out_w^T  -> d_out
    gemm_mma<4><<<dim3(DMODEL / 128, TOKENS / 128), 256>>>(
        attnb, out_w, out, x, TOKENS, DMODEL, DMODEL);

    // 6. hn = rmsnorm(x1, ln2_w)
    rmsnorm_kernel<<<TOKENS, 256>>>(out, ln2_w, hn);

    // 7. g = silu(hn @ wg^T)   [4096, 4096]
    gemm_mma<2><<<dim3(DFF / 128, TOKENS / 128), 256>>>(
        hn, wg, gb, nullptr, TOKENS, DFF, DMODEL);

    // 8. act = g * (hn @ wu^T)   [4096, 4096]
    gemm_mma<3><<<dim3(DFF / 128, TOKENS / 128), 256>>>(
        hn, wu, ub, gb, TOKENS, DFF, DMODEL);

    // 9. out = x1 + act @ wo^T   (in-place residual add on d_out)
    gemm_mma<4><<<dim3(DMODEL / 128, TOKENS / 128), 256>>>(
        ub, wo, out, out, TOKENS, DMODEL, DFF);
}

// round 4
// speedup vs baseline: 2.9350x; 1.4136x over previous
#include <cuda_runtime.h>
#include <cuda_bf16.h>
#include <math.h>
#include <cstdint>

// ---------------------------------------------------------------------------
// Problem constants
// ---------------------------------------------------------------------------
#define TOKENS   4096           // B*T = 2*2048
#define TSEQ     2048
#define DMODEL   1024
#define NHEADS   16
#define DHEAD    64
#define DFF      4096
#define WINDOW   256

// ---------------------------------------------------------------------------
// Scratch (device globals; no runtime allocation allowed)
// ---------------------------------------------------------------------------
__device__ float g_xn  [(size_t)TOKENS * DMODEL];      // rmsnorm1 out (tf32-rounded)
__device__ float g_qkv [(size_t)TOKENS * 3 * DMODEL];  // qkv projections (fp32)
__device__ float g_gate[(size_t)TOKENS * DMODEL];      // sigmoid gate (fp32)
__device__ float g_attn[(size_t)TOKENS * DMODEL];      // gated attn out (tf32-rounded)
__device__ float g_hn  [(size_t)TOKENS * DMODEL];      // rmsnorm2 out (tf32-rounded)
__device__ float g_g   [(size_t)TOKENS * DFF];         // silu(h@wg.T) (fp32)
__device__ float g_u   [(size_t)TOKENS * DFF];         // silu*u (tf32-rounded)
// pre-rounded weights
__device__ float g_wqkv [(size_t)3 * DMODEL * DMODEL];
__device__ float g_wgate[(size_t)DMODEL * DMODEL];
__device__ float g_wout [(size_t)DMODEL * DMODEL];
__device__ float g_wg   [(size_t)DFF * DMODEL];
__device__ float g_wu   [(size_t)DFF * DMODEL];
__device__ float g_wo   [(size_t)DMODEL * DFF];

// ---------------------------------------------------------------------------
// Helpers
// ---------------------------------------------------------------------------
__device__ __forceinline__ float sigmoid_f(float x) {
    return 1.0f / (1.0f + __expf(-x));
}

__device__ __forceinline__ uint32_t f2tf32(float x) {
    uint32_t r;
    asm("cvt.rna.tf32.f32 %0, %1;" : "=r"(r) : "f"(x));
    return r;
}
__device__ __forceinline__ float round_tf32f(float x) {
    return __uint_as_float(f2tf32(x));
}

__device__ __forceinline__ uint32_t smem_u32(const void* p) {
    uint32_t a;
    asm("{ .reg .u64 t; cvta.to.shared.u64 t, %1; cvt.u32.u64 %0, t; }"
        : "=r"(a) : "l"(p));
    return a;
}

__device__ __forceinline__ void cp16(uint32_t dst, const void* src) {
    asm volatile("cp.async.cg.shared.global [%0], [%1], 16;"
                 :: "r"(dst), "l"(src) : "memory");
}
#define CP_COMMIT() asm volatile("cp.async.commit_group;" ::: "memory")
#define CP_WAIT(n)  asm volatile("cp.async.wait_group %0;" :: "n"(n) : "memory")

__device__ __forceinline__ void mma_tf32(float* d, const uint32_t* a, const uint32_t* b) {
    asm volatile(
        "mma.sync.aligned.m16n8k8.row.col.f32.tf32.tf32.f32 "
        "{%0,%1,%2,%3}, {%4,%5,%6,%7}, {%8,%9}, {%0,%1,%2,%3};"
        : "+f"(d[0]), "+f"(d[1]), "+f"(d[2]), "+f"(d[3])
        : "r"(a[0]), "r"(a[1]), "r"(a[2]), "r"(a[3]), "r"(b[0]), "r"(b[1]));
}

// ---------------------------------------------------------------------------
// Weight pre-round: dst = tf32_round(src)
// ---------------------------------------------------------------------------
__global__ void __launch_bounds__(256) round_kernel(
    const float* __restrict__ src, float* __restrict__ dst, int n4)
{
    int i = blockIdx.x * 256 + threadIdx.x;
    if (i < n4) {
        float4 v = ((const float4*)src)[i];
        v.x = round_tf32f(v.x); v.y = round_tf32f(v.y);
        v.z = round_tf32f(v.z); v.w = round_tf32f(v.w);
        ((float4*)dst)[i] = v;
    }
}

// ---------------------------------------------------------------------------
// RMSNorm (tf32-rounded output): one block per row of 1024 floats
// ---------------------------------------------------------------------------
__global__ void __launch_bounds__(256) rmsnorm_kernel(
    const float* __restrict__ x, const float* __restrict__ w,
    float* __restrict__ out)
{
    __shared__ float warp_sums[8];
    int row = blockIdx.x;
    int tid = threadIdx.x;
    const float4* x4 = (const float4*)(x + (size_t)row * DMODEL);
    const float4* w4 = (const float4*)w;
    float4 xv = x4[tid];
    float ss = xv.x * xv.x + xv.y * xv.y + xv.z * xv.z + xv.w * xv.w;
    #pragma unroll
    for (int o = 16; o > 0; o >>= 1) ss += __shfl_xor_sync(0xffffffffu, ss, o);
    if ((tid & 31) == 0) warp_sums[tid >> 5] = ss;
    __syncthreads();
    if (tid < 8) {
        float v = warp_sums[tid];
        #pragma unroll
        for (int o = 4; o > 0; o >>= 1) v += __shfl_xor_sync(0xffu, v, o);
        if (tid == 0) warp_sums[0] = v;
    }
    __syncthreads();
    float scale = rsqrtf(warp_sums[0] * (1.0f / DMODEL) + 1e-6f);
    float4 wv = w4[tid];
    float4 r;
    r.x = round_tf32f(xv.x * scale * wv.x);
    r.y = round_tf32f(xv.y * scale * wv.y);
    r.z = round_tf32f(xv.z * scale * wv.z);
    r.w = round_tf32f(xv.w * scale * wv.w);
    ((float4*)(out + (size_t)row * DMODEL))[tid] = r;
}

// ---------------------------------------------------------------------------
// Tensor-core tf32 GEMM (NT), cp.async 4-stage pipeline.
// C[M,N] = A[M,K]*B[N,K]^T; A,B hold tf32-rounded fp32 bits.
// CTA tile 128x128, BK=16, 256 threads, warp tile 64x32 (2x4 warp grid).
// SMEM row stride 80B -> conflict-free LDS.32 fragment loads.
// EPI: 0=none 1=sigmoid 2=silu 3=mul aux 4=add aux; ROUND: tf32-round output.
// ---------------------------------------------------------------------------
#define ROWB 80
#define ASZ  (128 * ROWB)          // 10240 bytes per matrix per stage
#define STAGEB (2 * ASZ)           // 20480
#define NSTAGE 4
#define GSMEM (NSTAGE * STAGEB)    // 81920

template <int EPI, int ROUND>
__global__ void __launch_bounds__(256) gemm_mma(
    const float* __restrict__ A, const float* __restrict__ B,
    float* __restrict__ C, const float* __restrict__ aux,
    int M, int N, int K)
{
    extern __shared__ __align__(16) unsigned char sm[];
    uint32_t sb = smem_u32(sm);

    int tid  = threadIdx.x;
    int warp = tid >> 5;
    int lane = tid & 31;
    int g = lane >> 2;
    int t = lane & 3;
    int m0 = blockIdx.y * 128;
    int n0 = blockIdx.x * 128;
    int wm = (warp & 1) * 64;
    int wn = (warp >> 1) * 32;

    const float* Ab = A + (size_t)m0 * K;
    const float* Bb = B + (size_t)n0 * K;

    int r0 = tid >> 2;        // 0..63
    int r1 = r0 + 64;
    int q  = tid & 3;
    uint32_t dA0 = r0 * ROWB + q * 16;
    uint32_t dA1 = r1 * ROWB + q * 16;

    float acc[4][4][4];
    #pragma unroll
    for (int f = 0; f < 4; f++)
        #pragma unroll
        for (int n = 0; n < 4; n++)
            #pragma unroll
            for (int i = 0; i < 4; i++) acc[f][n][i] = 0.0f;

    int nch = K >> 4;

    // ---- prologue: stages 0..2 ----
    #pragma unroll
    for (int s = 0; s < NSTAGE - 1; s++) {
        int k0 = s << 4;
        uint32_t so = sb + s * STAGEB;
        cp16(so + dA0, Ab + (size_t)r0 * K + k0 + q * 4);
        cp16(so + dA1, Ab + (size_t)r1 * K + k0 + q * 4);
        cp16(so + ASZ + dA0, Bb + (size_t)r0 * K + k0 + q * 4);
        cp16(so + ASZ + dA1, Bb + (size_t)r1 * K + k0 + q * 4);
        CP_COMMIT();
    }

    for (int c = 0; c < nch; c++) {
        if (c + NSTAGE - 1 < nch) { CP_WAIT(2); } else { CP_WAIT(0); }
        __syncthreads();

        if (c + NSTAGE - 1 < nch) {
            int s = (c + NSTAGE - 1) & (NSTAGE - 1);
            int k0 = (c + NSTAGE - 1) << 4;
            uint32_t so = sb + s * STAGEB;
            cp16(so + dA0, Ab + (size_t)r0 * K + k0 + q * 4);
            cp16(so + dA1, Ab + (size_t)r1 * K + k0 + q * 4);
            cp16(so + ASZ + dA0, Bb + (size_t)r0 * K + k0 + q * 4);
            cp16(so + ASZ + dA1, Bb + (size_t)r1 * K + k0 + q * 4);
            CP_COMMIT();
        }

        const unsigned char* As = sm + (c & (NSTAGE - 1)) * STAGEB;
        const unsigned char* Bs = As + ASZ;

        uint32_t af[4][2][4];
        uint32_t bf[4][4];
        #pragma unroll
        for (int f = 0; f < 4; f++) {
            #pragma unroll
            for (int h = 0; h < 2; h++) {
                const unsigned char* p = As + (wm + f * 16 + h * 8 + g) * ROWB + t * 4;
                af[f][h][0] = *(const uint32_t*)(p);
                af[f][h][1] = *(const uint32_t*)(p + 16);
                af[f][h][2] = *(const uint32_t*)(p + 32);
                af[f][h][3] = *(const uint32_t*)(p + 48);
            }
        }
        #pragma unroll
        for (int n = 0; n < 4; n++) {
            const unsigned char* p = Bs + (wn + n * 8 + g) * ROWB + t * 4;
            bf[n][0] = *(const uint32_t*)(p);
            bf[n][1] = *(const uint32_t*)(p + 16);
            bf[n][2] = *(const uint32_t*)(p + 32);
            bf[n][3] = *(const uint32_t*)(p + 48);
        }
        #pragma unroll
        for (int f = 0; f < 4; f++) {
            #pragma unroll
            for (int n = 0; n < 4; n++) {
                uint32_t a0[4] = { af[f][0][0], af[f][1][0], af[f][0][1], af[f][1][1] };
                uint32_t b0[2] = { bf[n][0], bf[n][1] };
                mma_tf32(acc[f][n], a0, b0);
                uint32_t a1[4] = { af[f][0][2], af[f][1][2], af[f][0][3], af[f][1][3] };
                uint32_t b1[2] = { bf[n][2], bf[n][3] };
                mma_tf32(acc[f][n], a1, b1);
            }
        }
        __syncthreads();
    }

    // ---- epilogue ----
    #pragma unroll
    for (int f = 0; f < 4; f++) {
        int rr = m0 + wm + f * 16 + g;
        #pragma unroll
        for (int n = 0; n < 4; n++) {
            int cc = n0 + wn + n * 8 + 2 * t;
            float v0 = acc[f][n][0], v1 = acc[f][n][1];
            float v2 = acc[f][n][2], v3 = acc[f][n][3];
            size_t i0 = (size_t)rr * N + cc;
            size_t i1 = (size_t)(rr + 8) * N + cc;
            if (EPI == 1) {
                v0 = sigmoid_f(v0); v1 = sigmoid_f(v1);
                v2 = sigmoid_f(v2); v3 = sigmoid_f(v3);
            } else if (EPI == 2) {
                v0 *= sigmoid_f(v0); v1 *= sigmoid_f(v1);
                v2 *= sigmoid_f(v2); v3 *= sigmoid_f(v3);
            } else if (EPI == 3) {
                float2 x0 = *(const float2*)(aux + i0);
                float2 x1 = *(const float2*)(aux + i1);
                v0 *= x0.x; v1 *= x0.y; v2 *= x1.x; v3 *= x1.y;
            } else if (EPI == 4) {
                float2 x0 = *(const float2*)(aux + i0);
                float2 x1 = *(const float2*)(aux + i1);
                v0 += x0.x; v1 += x0.y; v2 += x1.x; v3 += x1.y;
            }
            if (ROUND) {
                v0 = round_tf32f(v0); v1 = round_tf32f(v1);
                v2 = round_tf32f(v2); v3 = round_tf32f(v3);
            }
            *(float2*)(C + i0) = make_float2(v0, v1);
            *(float2*)(C + i1) = make_float2(v2, v3);
        }
    }
}

// ---------------------------------------------------------------------------
// Sliding-window causal attention with fused gate (tf32-rounded output).
// ---------------------------------------------------------------------------
__global__ void __launch_bounds__(128) attn_kernel(
    const float* __restrict__ qkv, const float* __restrict__ gate,
    float* __restrict__ out)
{
    __shared__ float4 Ks[64 * 16];
    __shared__ float4 Vs[64 * 16];

    int tid  = threadIdx.x;
    int row  = tid >> 1;
    int half = tid & 1;
    int b = blockIdx.y >> 4;
    int h = blockIdx.y & 15;
    int q0 = blockIdx.x * 64;
    int qi = q0 + row;
    size_t tq = (size_t)b * TSEQ + qi;

    const float4* qp = (const float4*)(qkv + tq * (3 * DMODEL) + h * DHEAD + half * 32);
    float4 qv[8];
    #pragma unroll
    for (int i = 0; i < 8; i++) qv[i] = qp[i];

    float4 o[8];
    #pragma unroll
    for (int i = 0; i < 8; i++) o[i] = make_float4(0.f, 0.f, 0.f, 0.f);
    float m = -1e30f, l = 0.0f;

    int s_lo = q0 - WINDOW;
    if (s_lo < 0) s_lo = 0;

    for (int s = s_lo; s <= q0; s += 64) {
        for (int i = tid; i < 1024; i += 128) {
            int key = i >> 4;
            int c   = i & 15;
            size_t base = ((size_t)b * TSEQ + s + key) * (3 * DMODEL) + h * DHEAD + c * 4;
            Ks[i] = *(const float4*)(qkv + base + DMODEL);
            Vs[i] = *(const float4*)(qkv + base + 2 * DMODEL);
        }
        __syncthreads();

        for (int j = 0; j < 64; ++j) {
            int k = s + j;
            int dist = qi - k;
            float p = 0.0f;
            const float4* kp = &Ks[j * 16 + half * 8];
            #pragma unroll
            for (int i = 0; i < 8; i++) {
                float4 kv = kp[i];
                p += qv[i].x * kv.x + qv[i].y * kv.y + qv[i].z * kv.z + qv[i].w * kv.w;
            }
            p += __shfl_xor_sync(0xffffffffu, p, 1);
            if (dist >= 0 && dist < WINDOW) {
                float sc = p * 0.125f;
                if (sc > m) {
                    float cfac = __expf(m - sc);
                    l *= cfac;
                    #pragma unroll
                    for (int i = 0; i < 8; i++) {
                        o[i].x *= cfac; o[i].y *= cfac;
                        o[i].z *= cfac; o[i].w *= cfac;
                    }
                    m = sc;
                }
                float pe = __expf(sc - m);
                l += pe;
                const float4* vp = &Vs[j * 16 + half * 8];
                #pragma unroll
                for (int i = 0; i < 8; i++) {
                    float4 vv = vp[i];
                    o[i].x += pe * vv.x; o[i].y += pe * vv.y;
                    o[i].z += pe * vv.z; o[i].w += pe * vv.w;
                }
            }
        }
        __syncthreads();
    }

    float inv = 1.0f / l;
    const float4* gp = (const float4*)(gate + tq * DMODEL + h * DHEAD + half * 32);
    float4* op = (float4*)(out + tq * DMODEL + h * DHEAD + half * 32);
    #pragma unroll
    for (int i = 0; i < 8; i++) {
        float4 g4 = gp[i];
        float4 v;
        v.x = round_tf32f(o[i].x * inv * g4.x);
        v.y = round_tf32f(o[i].y * inv * g4.y);
        v.z = round_tf32f(o[i].z * inv * g4.z);
        v.w = round_tf32f(o[i].w * inv * g4.w);
        op[i] = v;
    }
}

// ---------------------------------------------------------------------------
// Launch
// ---------------------------------------------------------------------------
extern "C" void kernel_launch(void* const* d_in, const int* in_sizes, int n_in,
                              void* d_out, int out_size)
{
    const float* x      = (const float*)d_in[0];
    const float* ln1_w  = (const float*)d_in[1];
    const float* qkv_w  = (const float*)d_in[2];
    const float* gate_w = (const float*)d_in[3];
    const float* out_w  = (const float*)d_in[4];
    const float* ln2_w  = (const float*)d_in[5];
    const float* wg     = (const float*)d_in[6];
    const float* wu     = (const float*)d_in[7];
    const float* wo     = (const float*)d_in[8];
    float* out = (float*)d_out;

    float *xn, *qkvb, *gateb, *attnb, *hn, *gb, *ub;
    float *wqkv, *wgate, *wout, *wgr, *wur, *wor;
    cudaGetSymbolAddress((void**)&xn,    g_xn);
    cudaGetSymbolAddress((void**)&qkvb,  g_qkv);
    cudaGetSymbolAddress((void**)&gateb, g_gate);
    cudaGetSymbolAddress((void**)&attnb, g_attn);
    cudaGetSymbolAddress((void**)&hn,    g_hn);
    cudaGetSymbolAddress((void**)&gb,    g_g);
    cudaGetSymbolAddress((void**)&ub,    g_u);
    cudaGetSymbolAddress((void**)&wqkv,  g_wqkv);
    cudaGetSymbolAddress((void**)&wgate, g_wgate);
    cudaGetSymbolAddress((void**)&wout,  g_wout);
    cudaGetSymbolAddress((void**)&wgr,   g_wg);
    cudaGetSymbolAddress((void**)&wur,   g_wu);
    cudaGetSymbolAddress((void**)&wor,   g_wo);

    cudaFuncSetAttribute(gemm_mma<0,0>, cudaFuncAttributeMaxDynamicSharedMemorySize, GSMEM);
    cudaFuncSetAttribute(gemm_mma<1,0>, cudaFuncAttributeMaxDynamicSharedMemorySize, GSMEM);
    cudaFuncSetAttribute(gemm_mma<2,0>, cudaFuncAttributeMaxDynamicSharedMemorySize, GSMEM);
    cudaFuncSetAttribute(gemm_mma<3,1>, cudaFuncAttributeMaxDynamicSharedMemorySize, GSMEM);
    cudaFuncSetAttribute(gemm_mma<4,0>, cudaFuncAttributeMaxDynamicSharedMemorySize, GSMEM);

    // 0. pre-round weights to tf32
    round_kernel<<<(3 * DMODEL * DMODEL / 4 + 255) / 256, 256>>>(qkv_w, wqkv, 3 * DMODEL * DMODEL / 4);
    round_kernel<<<(DMODEL * DMODEL / 4 + 255) / 256, 256>>>(gate_w, wgate, DMODEL * DMODEL / 4);
    round_kernel<<<(DMODEL * DMODEL / 4 + 255) / 256, 256>>>(out_w, wout, DMODEL * DMODEL / 4);
    round_kernel<<<(DFF * DMODEL / 4 + 255) / 256, 256>>>(wg, wgr, DFF * DMODEL / 4);
    round_kernel<<<(DFF * DMODEL / 4 + 255) / 256, 256>>>(wu, wur, DFF * DMODEL / 4);
    round_kernel<<<(DMODEL * DFF / 4 + 255) / 256, 256>>>(wo, wor, DMODEL * DFF / 4);

    // 1. xn = rmsnorm(x, ln1_w)   (tf32-rounded)
    rmsnorm_kernel<<<TOKENS, 256>>>(x, ln1_w, xn);

    // 2. qkv = xn @ qkv_w^T          [4096, 3072]
    gemm_mma<0,0><<<dim3(3 * DMODEL / 128, TOKENS / 128), 256, GSMEM>>>(
        xn, wqkv, qkvb, nullptr, TOKENS, 3 * DMODEL, DMODEL);

    // 3. gate = sigmoid(xn @ gate_w^T)   [4096, 1024]
    gemm_mma<1,0><<<dim3(DMODEL / 128, TOKENS / 128), 256, GSMEM>>>(
        xn, wgate, gateb, nullptr, TOKENS, DMODEL, DMODEL);

    // 4. attn = sliding-window attention, gated (tf32-rounded)
    attn_kernel<<<dim3(TSEQ / 64, 2 * NHEADS), 128>>>(qkvb, gateb, attnb);

    // 5. x1 = x + attn @ out_w^T  -> d_out (full fp32)
    gemm_mma<4,0><<<dim3(DMODEL / 128, TOKENS / 128), 256, GSMEM>>>(
        attnb, wout, out, x, TOKENS, DMODEL, DMODEL);

    // 6. hn = rmsnorm(x1, ln2_w)  (tf32-rounded)
    rmsnorm_kernel<<<TOKENS, 256>>>(out, ln2_w, hn);

    // 7. g = silu(hn @ wg^T)   [4096, 4096]
    gemm_mma<2,0><<<dim3(DFF / 128, TOKENS / 128), 256, GSMEM>>>(
        hn, wgr, gb, nullptr, TOKENS, DFF, DMODEL);

    // 8. act = g * (hn @ wu^T)   [4096, 4096]  (tf32-rounded output)
    gemm_mma<3,1><<<dim3(DFF / 128, TOKENS / 128), 256, GSMEM>>>(
        hn, wur, ub, gb, TOKENS, DFF, DMODEL);

    // 9. out = x1 + act @ wo^T   (in-place residual add on d_out)
    gemm_mma<4,0><<<dim3(DMODEL / 128, TOKENS / 128), 256, GSMEM>>>(
        ub, wor, out, out, TOKENS, DMODEL, DFF);
}

// round 5
// speedup vs baseline: 3.3877x; 1.1543x over previous
#include <cuda_runtime.h>
#include <cuda_fp16.h>
#include <math.h>
#include <cstdint>

// ---------------------------------------------------------------------------
// Problem constants
// ---------------------------------------------------------------------------
#define TOKENS   4096           // B*T = 2*2048
#define TSEQ     2048
#define DMODEL   1024
#define NHEADS   16
#define DHEAD    64
#define DFF      4096
#define WINDOW   256

// ---------------------------------------------------------------------------
// Scratch (device globals; no runtime allocation allowed)
// ---------------------------------------------------------------------------
__device__ __half g_xn_h [(size_t)TOKENS * DMODEL];     // rmsnorm1 out (fp16)
__device__ float  g_qkv  [(size_t)TOKENS * 3 * DMODEL]; // qkv (fp32, attn input)
__device__ float  g_gate [(size_t)TOKENS * DMODEL];     // sigmoid gate (fp32)
__device__ __half g_attn_h[(size_t)TOKENS * DMODEL];    // gated attn out (fp16)
__device__ __half g_hn_h [(size_t)TOKENS * DMODEL];     // rmsnorm2 out (fp16)
__device__ float  g_g    [(size_t)TOKENS * DFF];        // silu(h@wg.T) (fp32)
__device__ __half g_u_h  [(size_t)TOKENS * DFF];        // silu*u (fp16)
// fp16 weights
__device__ __half g_wqg [(size_t)4 * DMODEL * DMODEL];  // [qkv_w; gate_w] fused
__device__ __half g_wout[(size_t)DMODEL * DMODEL];
__device__ __half g_wg  [(size_t)DFF * DMODEL];
__device__ __half g_wu  [(size_t)DFF * DMODEL];
__device__ __half g_wo  [(size_t)DMODEL * DFF];

// ---------------------------------------------------------------------------
// Helpers
// ---------------------------------------------------------------------------
__device__ __forceinline__ float sigmoid_f(float x) {
    return 1.0f / (1.0f + __expf(-x));
}

__device__ __forceinline__ uint32_t smem_u32(const void* p) {
    uint32_t a;
    asm("{ .reg .u64 t; cvta.to.shared.u64 t, %1; cvt.u32.u64 %0, t; }"
        : "=r"(a) : "l"(p));
    return a;
}

__device__ __forceinline__ void cp16(uint32_t dst, const void* src) {
    asm volatile("cp.async.cg.shared.global [%0], [%1], 16;"
                 :: "r"(dst), "l"(src) : "memory");
}
#define CP_COMMIT() asm volatile("cp.async.commit_group;" ::: "memory")
#define CP_WAIT(n)  asm volatile("cp.async.wait_group %0;" :: "n"(n) : "memory")

__device__ __forceinline__ void mma_f16(float* d, const uint32_t* a, const uint32_t* b) {
    asm volatile(
        "mma.sync.aligned.m16n8k16.row.col.f32.f16.f16.f32 "
        "{%0,%1,%2,%3}, {%4,%5,%6,%7}, {%8,%9}, {%0,%1,%2,%3};"
        : "+f"(d[0]), "+f"(d[1]), "+f"(d[2]), "+f"(d[3])
        : "r"(a[0]), "r"(a[1]), "r"(a[2]), "r"(a[3]), "r"(b[0]), "r"(b[1]));
}

// ---------------------------------------------------------------------------
// Weight fp32 -> fp16 convert
// ---------------------------------------------------------------------------
__global__ void __launch_bounds__(256) w2h_kernel(
    const float* __restrict__ src, __half* __restrict__ dst, int n4)
{
    int i = blockIdx.x * 256 + threadIdx.x;
    if (i < n4) {
        float4 v = ((const float4*)src)[i];
        __half2 h0 = __floats2half2_rn(v.x, v.y);
        __half2 h1 = __floats2half2_rn(v.z, v.w);
        __half2* p = (__half2*)(dst + (size_t)i * 4);
        p[0] = h0; p[1] = h1;
    }
}

// ---------------------------------------------------------------------------
// RMSNorm (fp16 output): one block per row of 1024 floats
// ---------------------------------------------------------------------------
__global__ void __launch_bounds__(256) rmsnorm_kernel(
    const float* __restrict__ x, const float* __restrict__ w,
    __half* __restrict__ out)
{
    __shared__ float warp_sums[8];
    int row = blockIdx.x;
    int tid = threadIdx.x;
    const float4* x4 = (const float4*)(x + (size_t)row * DMODEL);
    const float4* w4 = (const float4*)w;
    float4 xv = x4[tid];
    float ss = xv.x * xv.x + xv.y * xv.y + xv.z * xv.z + xv.w * xv.w;
    #pragma unroll
    for (int o = 16; o > 0; o >>= 1) ss += __shfl_xor_sync(0xffffffffu, ss, o);
    if ((tid & 31) == 0) warp_sums[tid >> 5] = ss;
    __syncthreads();
    if (tid < 8) {
        float v = warp_sums[tid];
        #pragma unroll
        for (int o = 4; o > 0; o >>= 1) v += __shfl_xor_sync(0xffu, v, o);
        if (tid == 0) warp_sums[0] = v;
    }
    __syncthreads();
    float scale = rsqrtf(warp_sums[0] * (1.0f / DMODEL) + 1e-6f);
    float4 wv = w4[tid];
    __half2 h0 = __floats2half2_rn(xv.x * scale * wv.x, xv.y * scale * wv.y);
    __half2 h1 = __floats2half2_rn(xv.z * scale * wv.z, xv.w * scale * wv.w);
    __half2* p = (__half2*)(out + (size_t)row * DMODEL + tid * 4);
    p[0] = h0; p[1] = h1;
}

// ---------------------------------------------------------------------------
// fp16 tensor-core GEMM (NT): C[M,N] = A[M,K]*B[N,K]^T, fp32 accumulate.
// CTA tile 128x256, BK=32, 256 threads, warp tile 64x64 (2x4 warp grid),
// 4-stage cp.async pipeline. SMEM row = 64B data + 16B pad (80B) ->
// conflict-free LDS.32 fragment loads (word idx 20g+t distinct mod 32).
// EPI: 0=none 1=sigmoid 2=silu 3=mul-aux(out fp16) 4=add-aux 5=qkv/gate split
// ---------------------------------------------------------------------------
#define ROWB   80
#define ASZ_A  (128 * ROWB)          // 10240
#define ASZ_B  (256 * ROWB)          // 20480
#define STAGEB (ASZ_A + ASZ_B)       // 30720
#define NSTAGE 4
#define GSMEM  (NSTAGE * STAGEB)     // 122880

template <int EPI, int HOUT>
__global__ void __launch_bounds__(256) gemm_h(
    const __half* __restrict__ A, const __half* __restrict__ B,
    void* __restrict__ Cv, const float* __restrict__ aux,
    int M, int N, int K)
{
    extern __shared__ __align__(16) unsigned char sm[];
    uint32_t sb = smem_u32(sm);

    int tid  = threadIdx.x;
    int warp = tid >> 5;
    int lane = tid & 31;
    int g = lane >> 2;
    int t = lane & 3;
    int m0 = blockIdx.y * 128;
    int n0 = blockIdx.x * 256;
    int wm = (warp & 1) * 64;
    int wn = (warp >> 1) * 64;

    const __half* Ab = A + (size_t)m0 * K;
    const __half* Bb = B + (size_t)n0 * K;

    // loader indices
    int ra0 = tid >> 2, qa = tid & 3;       // A rows 0..63, +64
    uint32_t dA0 = ra0 * ROWB + qa * 16;
    uint32_t dA1 = (ra0 + 64) * ROWB + qa * 16;

    float acc[4][8][4];
    #pragma unroll
    for (int f = 0; f < 4; f++)
        #pragma unroll
        for (int n = 0; n < 8; n++)
            #pragma unroll
            for (int i = 0; i < 4; i++) acc[f][n][i] = 0.0f;

    int nch = K >> 5;

    // ---- prologue ----
    #pragma unroll
    for (int s = 0; s < NSTAGE - 1; s++) {
        int k0 = s << 5;
        uint32_t so = sb + s * STAGEB;
        cp16(so + dA0, Ab + (size_t)ra0 * K + k0 + qa * 8);
        cp16(so + dA1, Ab + (size_t)(ra0 + 64) * K + k0 + qa * 8);
        #pragma unroll
        for (int j = 0; j < 4; j++) {
            int idx = tid + j * 256;
            int rb = idx >> 2, qb = idx & 3;
            cp16(so + ASZ_A + rb * ROWB + qb * 16,
                 Bb + (size_t)rb * K + k0 + qb * 8);
        }
        CP_COMMIT();
    }

    for (int c = 0; c < nch; c++) {
        if (c + NSTAGE - 1 < nch) { CP_WAIT(2); } else { CP_WAIT(0); }
        __syncthreads();

        if (c + NSTAGE - 1 < nch) {
            int s = (c + NSTAGE - 1) & (NSTAGE - 1);
            int k0 = (c + NSTAGE - 1) << 5;
            uint32_t so = sb + s * STAGEB;
            cp16(so + dA0, Ab + (size_t)ra0 * K + k0 + qa * 8);
            cp16(so + dA1, Ab + (size_t)(ra0 + 64) * K + k0 + qa * 8);
            #pragma unroll
            for (int j = 0; j < 4; j++) {
                int idx = tid + j * 256;
                int rb = idx >> 2, qb = idx & 3;
                cp16(so + ASZ_A + rb * ROWB + qb * 16,
                     Bb + (size_t)rb * K + k0 + qb * 8);
            }
            CP_COMMIT();
        }

        const unsigned char* As = sm + (c & (NSTAGE - 1)) * STAGEB;
        const unsigned char* Bs = As + ASZ_A;

        #pragma unroll
        for (int ks = 0; ks < 2; ks++) {
            int kb = ks * 32;   // byte offset of 16-k group
            uint32_t af[4][4];
            uint32_t bf[8][2];
            #pragma unroll
            for (int f = 0; f < 4; f++) {
                const unsigned char* p0 = As + (wm + f * 16 + g) * ROWB + kb + t * 4;
                const unsigned char* p1 = p0 + 8 * ROWB;
                af[f][0] = *(const uint32_t*)(p0);
                af[f][1] = *(const uint32_t*)(p1);
                af[f][2] = *(const uint32_t*)(p0 + 16);
                af[f][3] = *(const uint32_t*)(p1 + 16);
            }
            #pragma unroll
            for (int n = 0; n < 8; n++) {
                const unsigned char* p = Bs + (wn + n * 8 + g) * ROWB + kb + t * 4;
                bf[n][0] = *(const uint32_t*)(p);
                bf[n][1] = *(const uint32_t*)(p + 16);
            }
            #pragma unroll
            for (int f = 0; f < 4; f++)
                #pragma unroll
                for (int n = 0; n < 8; n++)
                    mma_f16(acc[f][n], af[f], bf[n]);
        }
        __syncthreads();
    }

    // ---- epilogue ----
    #pragma unroll
    for (int f = 0; f < 4; f++) {
        int rr = m0 + wm + f * 16 + g;
        #pragma unroll
        for (int n = 0; n < 8; n++) {
            int gc = n0 + wn + n * 8 + 2 * t;
            float v0 = acc[f][n][0], v1 = acc[f][n][1];
            float v2 = acc[f][n][2], v3 = acc[f][n][3];
            if (EPI == 5) {
                // qkv/gate split at col 3072 (uniform per CTA since n0 % 256 == 0)
                if (n0 >= 3 * DMODEL) {
                    int cc = gc - 3 * DMODEL;
                    float* G = (float*)aux;  // gate buffer
                    G[(size_t)rr * DMODEL + cc]       = sigmoid_f(v0);
                    G[(size_t)rr * DMODEL + cc + 1]   = sigmoid_f(v1);
                    G[(size_t)(rr + 8) * DMODEL + cc]     = sigmoid_f(v2);
                    G[(size_t)(rr + 8) * DMODEL + cc + 1] = sigmoid_f(v3);
                } else {
                    float* Q = (float*)Cv;
                    *(float2*)(Q + (size_t)rr * (3 * DMODEL) + gc)       = make_float2(v0, v1);
                    *(float2*)(Q + (size_t)(rr + 8) * (3 * DMODEL) + gc) = make_float2(v2, v3);
                }
                continue;
            }
            size_t i0 = (size_t)rr * N + gc;
            size_t i1 = (size_t)(rr + 8) * N + gc;
            if (EPI == 1) {
                v0 = sigmoid_f(v0); v1 = sigmoid_f(v1);
                v2 = sigmoid_f(v2); v3 = sigmoid_f(v3);
            } else if (EPI == 2) {
                v0 *= sigmoid_f(v0); v1 *= sigmoid_f(v1);
                v2 *= sigmoid_f(v2); v3 *= sigmoid_f(v3);
            } else if (EPI == 3) {
                float2 x0 = *(const float2*)(aux + i0);
                float2 x1 = *(const float2*)(aux + i1);
                v0 *= x0.x; v1 *= x0.y; v2 *= x1.x; v3 *= x1.y;
            } else if (EPI == 4) {
                float2 x0 = *(const float2*)(aux + i0);
                float2 x1 = *(const float2*)(aux + i1);
                v0 += x0.x; v1 += x0.y; v2 += x1.x; v3 += x1.y;
            }
            if (HOUT) {
                __half* C = (__half*)Cv;
                *(__half2*)(C + i0) = __floats2half2_rn(v0, v1);
                *(__half2*)(C + i1) = __floats2half2_rn(v2, v3);
            } else {
                float* C = (float*)Cv;
                *(float2*)(C + i0) = make_float2(v0, v1);
                *(float2*)(C + i1) = make_float2(v2, v3);
            }
        }
    }
}

// ---------------------------------------------------------------------------
// Sliding-window causal attention with fused gate. 4 lanes per q-row,
// 256 threads / 64 q-rows per block. Output fp16.
// ---------------------------------------------------------------------------
__global__ void __launch_bounds__(256) attn_kernel(
    const float* __restrict__ qkv, const float* __restrict__ gate,
    __half* __restrict__ out)
{
    __shared__ float4 Ks[64 * 16];
    __shared__ float4 Vs[64 * 16];

    int tid = threadIdx.x;
    int row = tid >> 2;
    int qtr = tid & 3;
    int b = blockIdx.y >> 4;
    int h = blockIdx.y & 15;
    int q0 = blockIdx.x * 64;
    int qi = q0 + row;
    size_t tq = (size_t)b * TSEQ + qi;

    const float4* qp = (const float4*)(qkv + tq * (3 * DMODEL) + h * DHEAD + qtr * 16);
    float4 qv[4];
    #pragma unroll
    for (int i = 0; i < 4; i++) qv[i] = qp[i];

    float4 o[4];
    #pragma unroll
    for (int i = 0; i < 4; i++) o[i] = make_float4(0.f, 0.f, 0.f, 0.f);
    float m = -1e30f, l = 0.0f;

    int s_lo = q0 - WINDOW;
    if (s_lo < 0) s_lo = 0;

    for (int s = s_lo; s <= q0; s += 64) {
        for (int i = tid; i < 1024; i += 256) {
            int key = i >> 4;
            int c   = i & 15;
            size_t base = ((size_t)b * TSEQ + s + key) * (3 * DMODEL) + h * DHEAD + c * 4;
            Ks[i] = *(const float4*)(qkv + base + DMODEL);
            Vs[i] = *(const float4*)(qkv + base + 2 * DMODEL);
        }
        __syncthreads();

        for (int j = 0; j < 64; ++j) {
            int k = s + j;
            int dist = qi - k;
            float p = 0.0f;
            const float4* kp = &Ks[j * 16 + qtr * 4];
            #pragma unroll
            for (int i = 0; i < 4; i++) {
                float4 kv = kp[i];
                p += qv[i].x * kv.x + qv[i].y * kv.y + qv[i].z * kv.z + qv[i].w * kv.w;
            }
            p += __shfl_xor_sync(0xffffffffu, p, 1);
            p += __shfl_xor_sync(0xffffffffu, p, 2);
            if (dist >= 0 && dist < WINDOW) {
                float sc = p * 0.125f;
                if (sc > m) {
                    float cfac = __expf(m - sc);
                    l *= cfac;
                    #pragma unroll
                    for (int i = 0; i < 4; i++) {
                        o[i].x *= cfac; o[i].y *= cfac;
                        o[i].z *= cfac; o[i].w *= cfac;
                    }
                    m = sc;
                }
                float pe = __expf(sc - m);
                l += pe;
                const float4* vp = &Vs[j * 16 + qtr * 4];
                #pragma unroll
                for (int i = 0; i < 4; i++) {
                    float4 vv = vp[i];
                    o[i].x += pe * vv.x; o[i].y += pe * vv.y;
                    o[i].z += pe * vv.z; o[i].w += pe * vv.w;
                }
            }
        }
        __syncthreads();
    }

    float inv = 1.0f / l;
    const float4* gp = (const float4*)(gate + tq * DMODEL + h * DHEAD + qtr * 16);
    __half2* op = (__half2*)(out + tq * DMODEL + h * DHEAD + qtr * 16);
    #pragma unroll
    for (int i = 0; i < 4; i++) {
        float4 g4 = gp[i];
        op[i * 2]     = __floats2half2_rn(o[i].x * inv * g4.x, o[i].y * inv * g4.y);
        op[i * 2 + 1] = __floats2half2_rn(o[i].z * inv * g4.z, o[i].w * inv * g4.w);
    }
}

// ---------------------------------------------------------------------------
// Launch
// ---------------------------------------------------------------------------
extern "C" void kernel_launch(void* const* d_in, const int* in_sizes, int n_in,
                              void* d_out, int out_size)
{
    const float* x      = (const float*)d_in[0];
    const float* ln1_w  = (const float*)d_in[1];
    const float* qkv_w  = (const float*)d_in[2];
    const float* gate_w = (const float*)d_in[3];
    const float* out_w  = (const float*)d_in[4];
    const float* ln2_w  = (const float*)d_in[5];
    const float* wg     = (const float*)d_in[6];
    const float* wu     = (const float*)d_in[7];
    const float* wo     = (const float*)d_in[8];
    float* out = (float*)d_out;

    float *qkvb, *gateb, *gb;
    __half *xnh, *attnh, *hnh, *ubh, *wqg, *wouth, *wgh, *wuh, *woh;
    cudaGetSymbolAddress((void**)&xnh,   g_xn_h);
    cudaGetSymbolAddress((void**)&qkvb,  g_qkv);
    cudaGetSymbolAddress((void**)&gateb, g_gate);
    cudaGetSymbolAddress((void**)&attnh, g_attn_h);
    cudaGetSymbolAddress((void**)&hnh,   g_hn_h);
    cudaGetSymbolAddress((void**)&gb,    g_g);
    cudaGetSymbolAddress((void**)&ubh,   g_u_h);
    cudaGetSymbolAddress((void**)&wqg,   g_wqg);
    cudaGetSymbolAddress((void**)&wouth, g_wout);
    cudaGetSymbolAddress((void**)&wgh,   g_wg);
    cudaGetSymbolAddress((void**)&wuh,   g_wu);
    cudaGetSymbolAddress((void**)&woh,   g_wo);

    cudaFuncSetAttribute(gemm_h<5,0>, cudaFuncAttributeMaxDynamicSharedMemorySize, GSMEM);
    cudaFuncSetAttribute(gemm_h<4,0>, cudaFuncAttributeMaxDynamicSharedMemorySize, GSMEM);
    cudaFuncSetAttribute(gemm_h<2,0>, cudaFuncAttributeMaxDynamicSharedMemorySize, GSMEM);
    cudaFuncSetAttribute(gemm_h<3,1>, cudaFuncAttributeMaxDynamicSharedMemorySize, GSMEM);

    // 0. weights -> fp16 ([qkv_w; gate_w] fused into one 4096x1024)
    w2h_kernel<<<(3 * DMODEL * DMODEL / 4 + 255) / 256, 256>>>(qkv_w, wqg, 3 * DMODEL * DMODEL / 4);
    w2h_kernel<<<(DMODEL * DMODEL / 4 + 255) / 256, 256>>>(gate_w, wqg + (size_t)3 * DMODEL * DMODEL, DMODEL * DMODEL / 4);
    w2h_kernel<<<(DMODEL * DMODEL / 4 + 255) / 256, 256>>>(out_w, wouth, DMODEL * DMODEL / 4);
    w2h_kernel<<<(DFF * DMODEL / 4 + 255) / 256, 256>>>(wg, wgh, DFF * DMODEL / 4);
    w2h_kernel<<<(DFF * DMODEL / 4 + 255) / 256, 256>>>(wu, wuh, DFF * DMODEL / 4);
    w2h_kernel<<<(DMODEL * DFF / 4 + 255) / 256, 256>>>(wo, woh, DMODEL * DFF / 4);

    // 1. xn = rmsnorm(x, ln1_w) -> fp16
    rmsnorm_kernel<<<TOKENS, 256>>>(x, ln1_w, xnh);

    // 2+3. fused qkv|gate GEMM: [4096, 4096]; cols<3072 -> qkvb, else sigmoid -> gateb
    gemm_h<5,0><<<dim3(4 * DMODEL / 256, TOKENS / 128), 256, GSMEM>>>(
        xnh, wqg, qkvb, gateb, TOKENS, 4 * DMODEL, DMODEL);

    // 4. attn -> fp16
    attn_kernel<<<dim3(TSEQ / 64, 2 * NHEADS), 256>>>(qkvb, gateb, attnh);

    // 5. x1 = x + attn @ out_w^T -> d_out (fp32)
    gemm_h<4,0><<<dim3(DMODEL / 256, TOKENS / 128), 256, GSMEM>>>(
        attnh, wouth, out, x, TOKENS, DMODEL, DMODEL);

    // 6. hn = rmsnorm(x1, ln2_w) -> fp16
    rmsnorm_kernel<<<TOKENS, 256>>>(out, ln2_w, hnh);

    // 7. g = silu(hn @ wg^T) -> fp32
    gemm_h<2,0><<<dim3(DFF / 256, TOKENS / 128), 256, GSMEM>>>(
        hnh, wgh, gb, nullptr, TOKENS, DFF, DMODEL);

    // 8. act = g * (hn @ wu^T) -> fp16
    gemm_h<3,1><<<dim3(DFF / 256, TOKENS / 128), 256, GSMEM>>>(
        hnh, wuh, ubh, gb, TOKENS, DFF, DMODEL);

    // 9. out = x1 + act @ wo^T (in-place residual on d_out)
    gemm_h<4,0><<<dim3(DMODEL / 256, TOKENS / 128), 256, GSMEM>>>(
        ubh, woh, out, out, TOKENS, DMODEL, DFF);
}

// round 6
// speedup vs baseline: 5.9889x; 1.7678x over previous
#include <cuda_runtime.h>
#include <cuda_fp16.h>
#include <math.h>
#include <cstdint>

// ---------------------------------------------------------------------------
// Problem constants
// ---------------------------------------------------------------------------
#define TOKENS   4096           // B*T = 2*2048
#define TSEQ     2048
#define DMODEL   1024
#define NHEADS   16
#define DHEAD    64
#define DFF      4096
#define WINDOW   256

// ---------------------------------------------------------------------------
// Scratch (device globals; no runtime allocation allowed)
// ---------------------------------------------------------------------------
__device__ __half g_xn_h [(size_t)TOKENS * DMODEL];     // rmsnorm1 out (fp16)
__device__ float  g_qkv  [(size_t)TOKENS * 3 * DMODEL]; // qkv (fp32, attn input)
__device__ float  g_gate [(size_t)TOKENS * DMODEL];     // sigmoid gate (fp32)
__device__ __half g_attn_h[(size_t)TOKENS * DMODEL];    // gated attn out (fp16)
__device__ __half g_hn_h [(size_t)TOKENS * DMODEL];     // rmsnorm2 out (fp16)
__device__ float  g_g    [(size_t)TOKENS * DFF];        // silu(h@wg.T) (fp32)
__device__ __half g_u_h  [(size_t)TOKENS * DFF];        // silu*u (fp16)
// fp16 weights
__device__ __half g_wqg [(size_t)4 * DMODEL * DMODEL];  // [qkv_w; gate_w] fused
__device__ __half g_wout[(size_t)DMODEL * DMODEL];
__device__ __half g_wg  [(size_t)DFF * DMODEL];
__device__ __half g_wu  [(size_t)DFF * DMODEL];
__device__ __half g_wo  [(size_t)DMODEL * DFF];

// ---------------------------------------------------------------------------
// Helpers
// ---------------------------------------------------------------------------
__device__ __forceinline__ float sigmoid_f(float x) {
    return 1.0f / (1.0f + __expf(-x));
}

__device__ __forceinline__ uint32_t smem_u32(const void* p) {
    uint32_t a;
    asm("{ .reg .u64 t; cvta.to.shared.u64 t, %1; cvt.u32.u64 %0, t; }"
        : "=r"(a) : "l"(p));
    return a;
}

__device__ __forceinline__ void cp16(uint32_t dst, const void* src) {
    asm volatile("cp.async.cg.shared.global [%0], [%1], 16;"
                 :: "r"(dst), "l"(src) : "memory");
}
#define CP_COMMIT() asm volatile("cp.async.commit_group;" ::: "memory")
#define CP_WAIT(n)  asm volatile("cp.async.wait_group %0;" :: "n"(n) : "memory")

__device__ __forceinline__ void mma_f16(float* d, const uint32_t* a, const uint32_t* b) {
    asm volatile(
        "mma.sync.aligned.m16n8k16.row.col.f32.f16.f16.f32 "
        "{%0,%1,%2,%3}, {%4,%5,%6,%7}, {%8,%9}, {%0,%1,%2,%3};"
        : "+f"(d[0]), "+f"(d[1]), "+f"(d[2]), "+f"(d[3])
        : "r"(a[0]), "r"(a[1]), "r"(a[2]), "r"(a[3]), "r"(b[0]), "r"(b[1]));
}

__device__ __forceinline__ void ldsm4(uint32_t& r0, uint32_t& r1,
                                      uint32_t& r2, uint32_t& r3, uint32_t addr) {
    asm volatile("ldmatrix.sync.aligned.m8n8.x4.shared.b16 {%0,%1,%2,%3}, [%4];"
                 : "=r"(r0), "=r"(r1), "=r"(r2), "=r"(r3) : "r"(addr));
}
__device__ __forceinline__ void ldsm4t(uint32_t& r0, uint32_t& r1,
                                       uint32_t& r2, uint32_t& r3, uint32_t addr) {
    asm volatile("ldmatrix.sync.aligned.m8n8.x4.trans.shared.b16 {%0,%1,%2,%3}, [%4];"
                 : "=r"(r0), "=r"(r1), "=r"(r2), "=r"(r3) : "r"(addr));
}

__device__ __forceinline__ uint32_t packh2(float lo, float hi) {
    __half2 h = __floats2half2_rn(lo, hi);
    return *(uint32_t*)&h;
}

// ---------------------------------------------------------------------------
// Weight fp32 -> fp16 convert
// ---------------------------------------------------------------------------
__global__ void __launch_bounds__(256) w2h_kernel(
    const float* __restrict__ src, __half* __restrict__ dst, int n4)
{
    int i = blockIdx.x * 256 + threadIdx.x;
    if (i < n4) {
        float4 v = ((const float4*)src)[i];
        __half2 h0 = __floats2half2_rn(v.x, v.y);
        __half2 h1 = __floats2half2_rn(v.z, v.w);
        __half2* p = (__half2*)(dst + (size_t)i * 4);
        p[0] = h0; p[1] = h1;
    }
}

// ---------------------------------------------------------------------------
// RMSNorm (fp16 output): one block per row of 1024 floats
// ---------------------------------------------------------------------------
__global__ void __launch_bounds__(256) rmsnorm_kernel(
    const float* __restrict__ x, const float* __restrict__ w,
    __half* __restrict__ out)
{
    __shared__ float warp_sums[8];
    int row = blockIdx.x;
    int tid = threadIdx.x;
    const float4* x4 = (const float4*)(x + (size_t)row * DMODEL);
    const float4* w4 = (const float4*)w;
    float4 xv = x4[tid];
    float ss = xv.x * xv.x + xv.y * xv.y + xv.z * xv.z + xv.w * xv.w;
    #pragma unroll
    for (int o = 16; o > 0; o >>= 1) ss += __shfl_xor_sync(0xffffffffu, ss, o);
    if ((tid & 31) == 0) warp_sums[tid >> 5] = ss;
    __syncthreads();
    if (tid < 8) {
        float v = warp_sums[tid];
        #pragma unroll
        for (int o = 4; o > 0; o >>= 1) v += __shfl_xor_sync(0xffu, v, o);
        if (tid == 0) warp_sums[0] = v;
    }
    __syncthreads();
    float scale = rsqrtf(warp_sums[0] * (1.0f / DMODEL) + 1e-6f);
    float4 wv = w4[tid];
    __half2 h0 = __floats2half2_rn(xv.x * scale * wv.x, xv.y * scale * wv.y);
    __half2 h1 = __floats2half2_rn(xv.z * scale * wv.z, xv.w * scale * wv.w);
    __half2* p = (__half2*)(out + (size_t)row * DMODEL + tid * 4);
    p[0] = h0; p[1] = h1;
}

// ---------------------------------------------------------------------------
// fp16 tensor-core GEMM (NT): C[M,N] = A[M,K]*B[N,K]^T, fp32 accumulate.
// CTA tile 128x256, BK=32, 256 threads, warp tile 64x64, 4-stage cp.async,
// ldmatrix.x4 fragment loads (80B row stride -> conflict-free).
// EPI: 0=none 1=sigmoid 2=silu 3=mul-aux 4=add-aux 5=qkv/gate split
// ---------------------------------------------------------------------------
#define ROWB   80
#define ASZ_A  (128 * ROWB)          // 10240
#define ASZ_B  (256 * ROWB)          // 20480
#define STAGEB (ASZ_A + ASZ_B)       // 30720
#define NSTAGE 4
#define GSMEM  (NSTAGE * STAGEB)     // 122880

template <int EPI, int HOUT>
__global__ void __launch_bounds__(256) gemm_h(
    const __half* __restrict__ A, const __half* __restrict__ B,
    void* __restrict__ Cv, const float* __restrict__ aux,
    int M, int N, int K)
{
    extern __shared__ __align__(16) unsigned char sm[];
    uint32_t sb = smem_u32(sm);

    int tid  = threadIdx.x;
    int warp = tid >> 5;
    int lane = tid & 31;
    int g = lane >> 2;
    int t = lane & 3;
    int m0 = blockIdx.y * 128;
    int n0 = blockIdx.x * 256;
    int wm = (warp & 1) * 64;
    int wn = (warp >> 1) * 64;

    const __half* Ab = A + (size_t)m0 * K;
    const __half* Bb = B + (size_t)n0 * K;

    int ra0 = tid >> 2, qa = tid & 3;
    uint32_t dA0 = ra0 * ROWB + qa * 16;
    uint32_t dA1 = (ra0 + 64) * ROWB + qa * 16;

    float acc[4][8][4];
    #pragma unroll
    for (int f = 0; f < 4; f++)
        #pragma unroll
        for (int n = 0; n < 8; n++)
            #pragma unroll
            for (int i = 0; i < 4; i++) acc[f][n][i] = 0.0f;

    int nch = K >> 5;

    #pragma unroll
    for (int s = 0; s < NSTAGE - 1; s++) {
        int k0 = s << 5;
        uint32_t so = sb + s * STAGEB;
        cp16(so + dA0, Ab + (size_t)ra0 * K + k0 + qa * 8);
        cp16(so + dA1, Ab + (size_t)(ra0 + 64) * K + k0 + qa * 8);
        #pragma unroll
        for (int j = 0; j < 4; j++) {
            int idx = tid + j * 256;
            int rb = idx >> 2, qb = idx & 3;
            cp16(so + ASZ_A + rb * ROWB + qb * 16,
                 Bb + (size_t)rb * K + k0 + qb * 8);
        }
        CP_COMMIT();
    }

    // ldmatrix lane-address components
    int la_r = (lane & 7) + ((lane >> 3) & 1) * 8;   // A row offset
    int la_c = ((lane >> 4) & 1) * 16;               // A col byte offset
    int lb_r = (lane & 7) + ((lane >> 4) & 1) * 8;   // B row offset
    int lb_c = ((lane >> 3) & 1) * 16;               // B col byte offset

    for (int c = 0; c < nch; c++) {
        if (c + NSTAGE - 1 < nch) { CP_WAIT(2); } else { CP_WAIT(0); }
        __syncthreads();

        if (c + NSTAGE - 1 < nch) {
            int s = (c + NSTAGE - 1) & (NSTAGE - 1);
            int k0 = (c + NSTAGE - 1) << 5;
            uint32_t so = sb + s * STAGEB;
            cp16(so + dA0, Ab + (size_t)ra0 * K + k0 + qa * 8);
            cp16(so + dA1, Ab + (size_t)(ra0 + 64) * K + k0 + qa * 8);
            #pragma unroll
            for (int j = 0; j < 4; j++) {
                int idx = tid + j * 256;
                int rb = idx >> 2, qb = idx & 3;
                cp16(so + ASZ_A + rb * ROWB + qb * 16,
                     Bb + (size_t)rb * K + k0 + qb * 8);
            }
            CP_COMMIT();
        }

        uint32_t sA = sb + (c & (NSTAGE - 1)) * STAGEB;
        uint32_t sB = sA + ASZ_A;

        #pragma unroll
        for (int ks = 0; ks < 2; ks++) {
            int kb = ks * 32;
            uint32_t af[4][4];
            uint32_t bf[8][2];
            #pragma unroll
            for (int f = 0; f < 4; f++) {
                uint32_t addr = sA + (wm + f * 16 + la_r) * ROWB + kb + la_c;
                ldsm4(af[f][0], af[f][1], af[f][2], af[f][3], addr);
            }
            #pragma unroll
            for (int np = 0; np < 4; np++) {
                uint32_t addr = sB + (wn + np * 16 + lb_r) * ROWB + kb + lb_c;
                ldsm4(bf[2 * np][0], bf[2 * np][1],
                      bf[2 * np + 1][0], bf[2 * np + 1][1], addr);
            }
            #pragma unroll
            for (int f = 0; f < 4; f++)
                #pragma unroll
                for (int n = 0; n < 8; n++)
                    mma_f16(acc[f][n], af[f], bf[n]);
        }
        __syncthreads();
    }

    // ---- epilogue ----
    #pragma unroll
    for (int f = 0; f < 4; f++) {
        int rr = m0 + wm + f * 16 + g;
        #pragma unroll
        for (int n = 0; n < 8; n++) {
            int gc = n0 + wn + n * 8 + 2 * t;
            float v0 = acc[f][n][0], v1 = acc[f][n][1];
            float v2 = acc[f][n][2], v3 = acc[f][n][3];
            if (EPI == 5) {
                if (n0 >= 3 * DMODEL) {
                    int cc = gc - 3 * DMODEL;
                    float* G = (float*)aux;
                    G[(size_t)rr * DMODEL + cc]           = sigmoid_f(v0);
                    G[(size_t)rr * DMODEL + cc + 1]       = sigmoid_f(v1);
                    G[(size_t)(rr + 8) * DMODEL + cc]     = sigmoid_f(v2);
                    G[(size_t)(rr + 8) * DMODEL + cc + 1] = sigmoid_f(v3);
                } else {
                    float* Q = (float*)Cv;
                    *(float2*)(Q + (size_t)rr * (3 * DMODEL) + gc)       = make_float2(v0, v1);
                    *(float2*)(Q + (size_t)(rr + 8) * (3 * DMODEL) + gc) = make_float2(v2, v3);
                }
                continue;
            }
            size_t i0 = (size_t)rr * N + gc;
            size_t i1 = (size_t)(rr + 8) * N + gc;
            if (EPI == 1) {
                v0 = sigmoid_f(v0); v1 = sigmoid_f(v1);
                v2 = sigmoid_f(v2); v3 = sigmoid_f(v3);
            } else if (EPI == 2) {
                v0 *= sigmoid_f(v0); v1 *= sigmoid_f(v1);
                v2 *= sigmoid_f(v2); v3 *= sigmoid_f(v3);
            } else if (EPI == 3) {
                float2 x0 = *(const float2*)(aux + i0);
                float2 x1 = *(const float2*)(aux + i1);
                v0 *= x0.x; v1 *= x0.y; v2 *= x1.x; v3 *= x1.y;
            } else if (EPI == 4) {
                float2 x0 = *(const float2*)(aux + i0);
                float2 x1 = *(const float2*)(aux + i1);
                v0 += x0.x; v1 += x0.y; v2 += x1.x; v3 += x1.y;
            }
            if (HOUT) {
                __half* C = (__half*)Cv;
                *(__half2*)(C + i0) = __floats2half2_rn(v0, v1);
                *(__half2*)(C + i1) = __floats2half2_rn(v2, v3);
            } else {
                float* C = (float*)Cv;
                *(float2*)(C + i0) = make_float2(v0, v1);
                *(float2*)(C + i1) = make_float2(v2, v3);
            }
        }
    }
}

// ---------------------------------------------------------------------------
// Tensor-core flash attention, sliding window, fused gate.
// Block = 64 q-rows of one (b,h); 4 warps (warp w owns q-rows w*16..w*16+15).
// Q*K^T and P*V via m16n8k16 fp16 MMA; online softmax in MMA C layout.
// smem row stride 72 halfs (144B) -> conflict-free ldmatrix.
// ---------------------------------------------------------------------------
__global__ void __launch_bounds__(128) attn_mma_kernel(
    const float* __restrict__ qkv, const float* __restrict__ gate,
    __half* __restrict__ out)
{
    __shared__ __align__(16) __half Qs[64 * 72];
    __shared__ __align__(16) __half Ks[64 * 72];
    __shared__ __align__(16) __half Vs[64 * 72];

    int tid = threadIdx.x;
    int warp = tid >> 5, lane = tid & 31;
    int g = lane >> 2, t = lane & 3;
    int b = blockIdx.y >> 4, h = blockIdx.y & 15;
    int q0 = blockIdx.x * 64;
    int wm16 = warp * 16;

    // load + convert Q tile [64 x 64]
    for (int i = tid; i < 1024; i += 128) {
        int row = i >> 4, c4 = i & 15;
        float4 v = *(const float4*)(qkv + ((size_t)(b * TSEQ + q0 + row)) * (3 * DMODEL)
                                    + h * DHEAD + c4 * 4);
        *(__half2*)(&Qs[row * 72 + c4 * 4])     = __floats2half2_rn(v.x, v.y);
        *(__half2*)(&Qs[row * 72 + c4 * 4 + 2]) = __floats2half2_rn(v.z, v.w);
    }
    __syncthreads();

    uint32_t qbase = smem_u32(Qs);
    uint32_t kbase = smem_u32(Ks);
    uint32_t vbase = smem_u32(Vs);

    int la_r = (lane & 7) + ((lane >> 3) & 1) * 8;   // A-tile row pattern
    int la_c = ((lane >> 4) & 1) * 8;                // A-tile col (halfs)
    int lb_r = (lane & 7) + ((lane >> 4) & 1) * 8;   // B-tile row pattern
    int lb_c = ((lane >> 3) & 1) * 8;                // B-tile col (halfs)

    // Q fragments (A-layout), 4 k-steps
    uint32_t qf[4][4];
    #pragma unroll
    for (int ks = 0; ks < 4; ks++) {
        uint32_t addr = qbase + ((wm16 + la_r) * 72 + ks * 16 + la_c) * 2;
        ldsm4(qf[ks][0], qf[ks][1], qf[ks][2], qf[ks][3], addr);
    }

    float oacc[8][4];
    #pragma unroll
    for (int n = 0; n < 8; n++)
        #pragma unroll
        for (int i = 0; i < 4; i++) oacc[n][i] = 0.0f;
    float m0 = -1e30f, m1 = -1e30f, l0 = 0.0f, l1 = 0.0f;
    int qi0 = q0 + wm16 + g;
    int qi1 = qi0 + 8;

    int s_lo = q0 - WINDOW;
    if (s_lo < 0) s_lo = 0;

    for (int s = s_lo; s <= q0; s += 64) {
        __syncthreads();   // protect K/V from previous iteration readers
        for (int i = tid; i < 1024; i += 128) {
            int row = i >> 4, c4 = i & 15;
            size_t base = ((size_t)(b * TSEQ + s + row)) * (3 * DMODEL) + h * DHEAD + c4 * 4;
            float4 kv = *(const float4*)(qkv + base + DMODEL);
            float4 vv = *(const float4*)(qkv + base + 2 * DMODEL);
            *(__half2*)(&Ks[row * 72 + c4 * 4])     = __floats2half2_rn(kv.x, kv.y);
            *(__half2*)(&Ks[row * 72 + c4 * 4 + 2]) = __floats2half2_rn(kv.z, kv.w);
            *(__half2*)(&Vs[row * 72 + c4 * 4])     = __floats2half2_rn(vv.x, vv.y);
            *(__half2*)(&Vs[row * 72 + c4 * 4 + 2]) = __floats2half2_rn(vv.z, vv.w);
        }
        __syncthreads();

        // S = Q * K^T  [16 x 64 per warp]
        float sacc[8][4];
        #pragma unroll
        for (int n = 0; n < 8; n++)
            #pragma unroll
            for (int i = 0; i < 4; i++) sacc[n][i] = 0.0f;

        #pragma unroll
        for (int ks = 0; ks < 4; ks++) {
            uint32_t bf[8][2];
            #pragma unroll
            for (int np = 0; np < 4; np++) {
                uint32_t addr = kbase + ((np * 16 + lb_r) * 72 + ks * 16 + lb_c) * 2;
                ldsm4(bf[2 * np][0], bf[2 * np][1],
                      bf[2 * np + 1][0], bf[2 * np + 1][1], addr);
            }
            #pragma unroll
            for (int nf = 0; nf < 8; nf++)
                mma_f16(sacc[nf], qf[ks], bf[nf]);
        }

        // mask + scale + online softmax
        float mt0 = -1e30f, mt1 = -1e30f;
        #pragma unroll
        for (int nf = 0; nf < 8; nf++) {
            int key = s + nf * 8 + 2 * t;
            #pragma unroll
            for (int c = 0; c < 2; c++) {
                unsigned d0 = (unsigned)(qi0 - (key + c));
                unsigned d1 = (unsigned)(qi1 - (key + c));
                float v0 = (d0 < (unsigned)WINDOW) ? sacc[nf][c] * 0.125f : -1e30f;
                float v1 = (d1 < (unsigned)WINDOW) ? sacc[nf][c + 2] * 0.125f : -1e30f;
                sacc[nf][c] = v0; sacc[nf][c + 2] = v1;
                mt0 = fmaxf(mt0, v0); mt1 = fmaxf(mt1, v1);
            }
        }
        mt0 = fmaxf(mt0, __shfl_xor_sync(0xffffffffu, mt0, 1));
        mt0 = fmaxf(mt0, __shfl_xor_sync(0xffffffffu, mt0, 2));
        mt1 = fmaxf(mt1, __shfl_xor_sync(0xffffffffu, mt1, 1));
        mt1 = fmaxf(mt1, __shfl_xor_sync(0xffffffffu, mt1, 2));

        float mn0 = fmaxf(m0, mt0), mn1 = fmaxf(m1, mt1);
        float cor0 = __expf(m0 - mn0), cor1 = __expf(m1 - mn1);
        m0 = mn0; m1 = mn1;
        l0 *= cor0; l1 *= cor1;
        #pragma unroll
        for (int nf = 0; nf < 8; nf++) {
            oacc[nf][0] *= cor0; oacc[nf][1] *= cor0;
            oacc[nf][2] *= cor1; oacc[nf][3] *= cor1;
        }
        float ps0 = 0.0f, ps1 = 0.0f;
        #pragma unroll
        for (int nf = 0; nf < 8; nf++) {
            #pragma unroll
            for (int c = 0; c < 2; c++) {
                float p0 = __expf(sacc[nf][c] - m0);
                float p1 = __expf(sacc[nf][c + 2] - m1);
                sacc[nf][c] = p0; sacc[nf][c + 2] = p1;
                ps0 += p0; ps1 += p1;
            }
        }
        l0 += ps0; l1 += ps1;

        // O += P * V
        #pragma unroll
        for (int kc = 0; kc < 4; kc++) {
            uint32_t pf[4];
            pf[0] = packh2(sacc[2 * kc][0],     sacc[2 * kc][1]);
            pf[1] = packh2(sacc[2 * kc][2],     sacc[2 * kc][3]);
            pf[2] = packh2(sacc[2 * kc + 1][0], sacc[2 * kc + 1][1]);
            pf[3] = packh2(sacc[2 * kc + 1][2], sacc[2 * kc + 1][3]);
            #pragma unroll
            for (int dp = 0; dp < 4; dp++) {
                uint32_t addr = vbase + ((kc * 16 + la_r) * 72 + dp * 16 + la_c) * 2;
                uint32_t v0, v1, v2, v3;
                ldsm4t(v0, v1, v2, v3, addr);
                uint32_t bb0[2] = { v0, v1 };
                uint32_t bb1[2] = { v2, v3 };
                mma_f16(oacc[2 * dp], pf, bb0);
                mma_f16(oacc[2 * dp + 1], pf, bb1);
            }
        }
    }

    // finalize
    l0 += __shfl_xor_sync(0xffffffffu, l0, 1);
    l0 += __shfl_xor_sync(0xffffffffu, l0, 2);
    l1 += __shfl_xor_sync(0xffffffffu, l1, 1);
    l1 += __shfl_xor_sync(0xffffffffu, l1, 2);
    float inv0 = 1.0f / l0, inv1 = 1.0f / l1;

    size_t tq0 = (size_t)b * TSEQ + qi0;
    size_t tq1 = tq0 + 8;
    #pragma unroll
    for (int nf = 0; nf < 8; nf++) {
        int col = h * DHEAD + nf * 8 + 2 * t;
        float2 g0 = *(const float2*)(gate + tq0 * DMODEL + col);
        float2 g1 = *(const float2*)(gate + tq1 * DMODEL + col);
        *(__half2*)(out + tq0 * DMODEL + col) =
            __floats2half2_rn(oacc[nf][0] * inv0 * g0.x, oacc[nf][1] * inv0 * g0.y);
        *(__half2*)(out + tq1 * DMODEL + col) =
            __floats2half2_rn(oacc[nf][2] * inv1 * g1.x, oacc[nf][3] * inv1 * g1.y);
    }
}

// ---------------------------------------------------------------------------
// Launch
// ---------------------------------------------------------------------------
extern "C" void kernel_launch(void* const* d_in, const int* in_sizes, int n_in,
                              void* d_out, int out_size)
{
    const float* x      = (const float*)d_in[0];
    const float* ln1_w  = (const float*)d_in[1];
    const float* qkv_w  = (const float*)d_in[2];
    const float* gate_w = (const float*)d_in[3];
    const float* out_w  = (const float*)d_in[4];
    const float* ln2_w  = (const float*)d_in[5];
    const float* wg     = (const float*)d_in[6];
    const float* wu     = (const float*)d_in[7];
    const float* wo     = (const float*)d_in[8];
    float* out = (float*)d_out;

    float *qkvb, *gateb, *gb;
    __half *xnh, *attnh, *hnh, *ubh, *wqg, *wouth, *wgh, *wuh, *woh;
    cudaGetSymbolAddress((void**)&xnh,   g_xn_h);
    cudaGetSymbolAddress((void**)&qkvb,  g_qkv);
    cudaGetSymbolAddress((void**)&gateb, g_gate);
    cudaGetSymbolAddress((void**)&attnh, g_attn_h);
    cudaGetSymbolAddress((void**)&hnh,   g_hn_h);
    cudaGetSymbolAddress((void**)&gb,    g_g);
    cudaGetSymbolAddress((void**)&ubh,   g_u_h);
    cudaGetSymbolAddress((void**)&wqg,   g_wqg);
    cudaGetSymbolAddress((void**)&wouth, g_wout);
    cudaGetSymbolAddress((void**)&wgh,   g_wg);
    cudaGetSymbolAddress((void**)&wuh,   g_wu);
    cudaGetSymbolAddress((void**)&woh,   g_wo);

    cudaFuncSetAttribute(gemm_h<5,0>, cudaFuncAttributeMaxDynamicSharedMemorySize, GSMEM);
    cudaFuncSetAttribute(gemm_h<4,0>, cudaFuncAttributeMaxDynamicSharedMemorySize, GSMEM);
    cudaFuncSetAttribute(gemm_h<2,0>, cudaFuncAttributeMaxDynamicSharedMemorySize, GSMEM);
    cudaFuncSetAttribute(gemm_h<3,1>, cudaFuncAttributeMaxDynamicSharedMemorySize, GSMEM);

    // 0. weights -> fp16 ([qkv_w; gate_w] fused)
    w2h_kernel<<<(3 * DMODEL * DMODEL / 4 + 255) / 256, 256>>>(qkv_w, wqg, 3 * DMODEL * DMODEL / 4);
    w2h_kernel<<<(DMODEL * DMODEL / 4 + 255) / 256, 256>>>(gate_w, wqg + (size_t)3 * DMODEL * DMODEL, DMODEL * DMODEL / 4);
    w2h_kernel<<<(DMODEL * DMODEL / 4 + 255) / 256, 256>>>(out_w, wouth, DMODEL * DMODEL / 4);
    w2h_kernel<<<(DFF * DMODEL / 4 + 255) / 256, 256>>>(wg, wgh, DFF * DMODEL / 4);
    w2h_kernel<<<(DFF * DMODEL / 4 + 255) / 256, 256>>>(wu, wuh, DFF * DMODEL / 4);
    w2h_kernel<<<(DMODEL * DFF / 4 + 255) / 256, 256>>>(wo, woh, DMODEL * DFF / 4);

    // 1. xn = rmsnorm(x, ln1_w) -> fp16
    rmsnorm_kernel<<<TOKENS, 256>>>(x, ln1_w, xnh);

    // 2+3. fused qkv|gate GEMM
    gemm_h<5,0><<<dim3(4 * DMODEL / 256, TOKENS / 128), 256, GSMEM>>>(
        xnh, wqg, qkvb, gateb, TOKENS, 4 * DMODEL, DMODEL);

    // 4. attn (tensor-core flash) -> fp16
    attn_mma_kernel<<<dim3(TSEQ / 64, 2 * NHEADS), 128>>>(qkvb, gateb, attnh);

    // 5. x1 = x + attn @ out_w^T -> d_out (fp32)
    gemm_h<4,0><<<dim3(DMODEL / 256, TOKENS / 128), 256, GSMEM>>>(
        attnh, wouth, out, x, TOKENS, DMODEL, DMODEL);

    // 6. hn = rmsnorm(x1, ln2_w) -> fp16
    rmsnorm_kernel<<<TOKENS, 256>>>(out, ln2_w, hnh);

    // 7. g = silu(hn @ wg^T) -> fp32
    gemm_h<2,0><<<dim3(DFF / 256, TOKENS / 128), 256, GSMEM>>>(
        hnh, wgh, gb, nullptr, TOKENS, DFF, DMODEL);

    // 8. act = g * (hn @ wu^T) -> fp16
    gemm_h<3,1><<<dim3(DFF / 256, TOKENS / 128), 256, GSMEM>>>(
        hnh, wuh, ubh, gb, TOKENS, DFF, DMODEL);

    // 9. out = x1 + act @ wo^T (in-place residual on d_out)
    gemm_h<4,0><<<dim3(DMODEL / 256, TOKENS / 128), 256, GSMEM>>>(
        ubh, woh, out, out, TOKENS, DMODEL, DFF);
}

// round 7
// speedup vs baseline: 6.8098x; 1.1371x over previous
#include <cuda_runtime.h>
#include <cuda_fp16.h>
#include <math.h>
#include <cstdint>

// ---------------------------------------------------------------------------
// Problem constants
// ---------------------------------------------------------------------------
#define TOKENS   4096           // B*T = 2*2048
#define TSEQ     2048
#define DMODEL   1024
#define NHEADS   16
#define DHEAD    64
#define DFF      4096
#define WINDOW   256

// ---------------------------------------------------------------------------
// Scratch (device globals; no runtime allocation allowed)
// ---------------------------------------------------------------------------
__device__ __half g_xn_h  [(size_t)TOKENS * DMODEL];      // rmsnorm1 out (fp16)
__device__ __half g_qkv_h [(size_t)TOKENS * 3 * DMODEL];  // qkv (fp16)
__device__ float  g_gate  [(size_t)TOKENS * DMODEL];      // sigmoid gate (fp32)
__device__ __half g_attn_h[(size_t)TOKENS * DMODEL];      // gated attn out (fp16)
__device__ __half g_hn_h  [(size_t)TOKENS * DMODEL];      // rmsnorm2 out (fp16)
__device__ __half g_u_h   [(size_t)TOKENS * DFF];         // silu(g)*u (fp16)
// fp16 weights
__device__ __half g_wqg [(size_t)4 * DMODEL * DMODEL];    // [qkv_w; gate_w]
__device__ __half g_wout[(size_t)DMODEL * DMODEL];
__device__ __half g_wf  [(size_t)2 * DFF * DMODEL];       // interleaved [wg_j; wu_j]
__device__ __half g_wo  [(size_t)DMODEL * DFF];

// ---------------------------------------------------------------------------
// Helpers
// ---------------------------------------------------------------------------
__device__ __forceinline__ float sigmoid_f(float x) {
    return 1.0f / (1.0f + __expf(-x));
}

__device__ __forceinline__ uint32_t smem_u32(const void* p) {
    uint32_t a;
    asm("{ .reg .u64 t; cvta.to.shared.u64 t, %1; cvt.u32.u64 %0, t; }"
        : "=r"(a) : "l"(p));
    return a;
}

__device__ __forceinline__ void cp16(uint32_t dst, const void* src) {
    asm volatile("cp.async.cg.shared.global [%0], [%1], 16;"
                 :: "r"(dst), "l"(src) : "memory");
}
#define CP_COMMIT() asm volatile("cp.async.commit_group;" ::: "memory")
#define CP_WAIT(n)  asm volatile("cp.async.wait_group %0;" :: "n"(n) : "memory")

__device__ __forceinline__ void mma_f16(float* d, const uint32_t* a, const uint32_t* b) {
    asm volatile(
        "mma.sync.aligned.m16n8k16.row.col.f32.f16.f16.f32 "
        "{%0,%1,%2,%3}, {%4,%5,%6,%7}, {%8,%9}, {%0,%1,%2,%3};"
        : "+f"(d[0]), "+f"(d[1]), "+f"(d[2]), "+f"(d[3])
        : "r"(a[0]), "r"(a[1]), "r"(a[2]), "r"(a[3]), "r"(b[0]), "r"(b[1]));
}

__device__ __forceinline__ void ldsm4(uint32_t& r0, uint32_t& r1,
                                      uint32_t& r2, uint32_t& r3, uint32_t addr) {
    asm volatile("ldmatrix.sync.aligned.m8n8.x4.shared.b16 {%0,%1,%2,%3}, [%4];"
                 : "=r"(r0), "=r"(r1), "=r"(r2), "=r"(r3) : "r"(addr));
}
__device__ __forceinline__ void ldsm4t(uint32_t& r0, uint32_t& r1,
                                       uint32_t& r2, uint32_t& r3, uint32_t addr) {
    asm volatile("ldmatrix.sync.aligned.m8n8.x4.trans.shared.b16 {%0,%1,%2,%3}, [%4];"
                 : "=r"(r0), "=r"(r1), "=r"(r2), "=r"(r3) : "r"(addr));
}

__device__ __forceinline__ uint32_t packh2(float lo, float hi) {
    __half2 h = __floats2half2_rn(lo, hi);
    return *(uint32_t*)&h;
}

// ---------------------------------------------------------------------------
// One-shot weight conversion (all 6 weights, one launch).
// wg/wu are row-interleaved into g_wf: row 2j = wg_j, row 2j+1 = wu_j.
// Segment sizes in float4 units.
// ---------------------------------------------------------------------------
#define S_QKV  786432      // 3*1024*1024/4
#define S_1M   262144      // 1024*1024/4
#define S_4M  1048576      // 4096*1024/4
#define W2H_TOT (S_QKV + 2*S_1M + 3*S_4M)   // 4456448

__global__ void __launch_bounds__(256) w2h_all(
    const float* __restrict__ qkv_w, const float* __restrict__ gate_w,
    const float* __restrict__ out_w, const float* __restrict__ wg,
    const float* __restrict__ wu, const float* __restrict__ wo,
    __half* __restrict__ wqg, __half* __restrict__ wouth,
    __half* __restrict__ wf, __half* __restrict__ woh)
{
    int i = blockIdx.x * 256 + threadIdx.x;
    const float* src;
    __half* dst;
    size_t doff;
    if (i < S_QKV) {
        src = qkv_w; dst = wqg; doff = (size_t)i * 4;
    } else if (i < S_QKV + S_1M) {
        int l = i - S_QKV;
        src = gate_w + (size_t)l * 4 - (size_t)i * 4;  // rebase below
        src = gate_w; dst = wqg + (size_t)3 * DMODEL * DMODEL;
        i = l; doff = (size_t)l * 4;
    } else if (i < S_QKV + 2 * S_1M) {
        int l = i - S_QKV - S_1M;
        src = out_w; dst = wouth; i = l; doff = (size_t)l * 4;
    } else if (i < S_QKV + 2 * S_1M + S_4M) {
        int l = i - S_QKV - 2 * S_1M;
        int row = l >> 8, c4 = l & 255;
        src = wg; dst = wf; i = l;
        doff = ((size_t)(2 * row)) * DMODEL + c4 * 4;
    } else if (i < S_QKV + 2 * S_1M + 2 * S_4M) {
        int l = i - S_QKV - 2 * S_1M - S_4M;
        int row = l >> 8, c4 = l & 255;
        src = wu; dst = wf; i = l;
        doff = ((size_t)(2 * row + 1)) * DMODEL + c4 * 4;
    } else {
        int l = i - S_QKV - 2 * S_1M - 2 * S_4M;
        src = wo; dst = woh; i = l; doff = (size_t)l * 4;
    }
    float4 v = ((const float4*)src)[i];
    __half2 h0 = __floats2half2_rn(v.x, v.y);
    __half2 h1 = __floats2half2_rn(v.z, v.w);
    __half2* p = (__half2*)(dst + doff);
    p[0] = h0; p[1] = h1;
}

// ---------------------------------------------------------------------------
// RMSNorm (fp16 output): one block per row of 1024 floats
// ---------------------------------------------------------------------------
__global__ void __launch_bounds__(256) rmsnorm_kernel(
    const float* __restrict__ x, const float* __restrict__ w,
    __half* __restrict__ out)
{
    __shared__ float warp_sums[8];
    int row = blockIdx.x;
    int tid = threadIdx.x;
    const float4* x4 = (const float4*)(x + (size_t)row * DMODEL);
    const float4* w4 = (const float4*)w;
    float4 xv = x4[tid];
    float ss = xv.x * xv.x + xv.y * xv.y + xv.z * xv.z + xv.w * xv.w;
    #pragma unroll
    for (int o = 16; o > 0; o >>= 1) ss += __shfl_xor_sync(0xffffffffu, ss, o);
    if ((tid & 31) == 0) warp_sums[tid >> 5] = ss;
    __syncthreads();
    if (tid < 8) {
        float v = warp_sums[tid];
        #pragma unroll
        for (int o = 4; o > 0; o >>= 1) v += __shfl_xor_sync(0xffu, v, o);
        if (tid == 0) warp_sums[0] = v;
    }
    __syncthreads();
    float scale = rsqrtf(warp_sums[0] * (1.0f / DMODEL) + 1e-6f);
    float4 wv = w4[tid];
    __half2 h0 = __floats2half2_rn(xv.x * scale * wv.x, xv.y * scale * wv.y);
    __half2 h1 = __floats2half2_rn(xv.z * scale * wv.z, xv.w * scale * wv.w);
    __half2* p = (__half2*)(out + (size_t)row * DMODEL + tid * 4);
    p[0] = h0; p[1] = h1;
}

// ---------------------------------------------------------------------------
// fp16 tensor-core GEMM (NT): C[M,N] = A[M,K]*B[N,K]^T, fp32 accumulate.
// CTA tile 128x256, BK=32, 256 threads, warp tile 64x64, 4-stage cp.async,
// ldmatrix.x4 fragment loads (80B row stride -> conflict-free).
// EPI: 4=add-aux(fp32 out) 5=qkv(fp16)/gate(fp32) split 6=FFN silu-interleave
// ---------------------------------------------------------------------------
#define ROWB   80
#define ASZ_A  (128 * ROWB)          // 10240
#define ASZ_B  (256 * ROWB)          // 20480
#define STAGEB (ASZ_A + ASZ_B)       // 30720
#define NSTAGE 4
#define GSMEM  (NSTAGE * STAGEB)     // 122880

template <int EPI>
__global__ void __launch_bounds__(256) gemm_h(
    const __half* __restrict__ A, const __half* __restrict__ B,
    void* __restrict__ Cv, const float* __restrict__ aux,
    int M, int N, int K)
{
    extern __shared__ __align__(16) unsigned char sm[];
    uint32_t sb = smem_u32(sm);

    int tid  = threadIdx.x;
    int warp = tid >> 5;
    int lane = tid & 31;
    int g = lane >> 2;
    int t = lane & 3;
    int m0 = blockIdx.y * 128;
    int n0 = blockIdx.x * 256;
    int wm = (warp & 1) * 64;
    int wn = (warp >> 1) * 64;

    const __half* Ab = A + (size_t)m0 * K;
    const __half* Bb = B + (size_t)n0 * K;

    int ra0 = tid >> 2, qa = tid & 3;
    uint32_t dA0 = ra0 * ROWB + qa * 16;
    uint32_t dA1 = (ra0 + 64) * ROWB + qa * 16;

    float acc[4][8][4];
    #pragma unroll
    for (int f = 0; f < 4; f++)
        #pragma unroll
        for (int n = 0; n < 8; n++)
            #pragma unroll
            for (int i = 0; i < 4; i++) acc[f][n][i] = 0.0f;

    int nch = K >> 5;

    #pragma unroll
    for (int s = 0; s < NSTAGE - 1; s++) {
        int k0 = s << 5;
        uint32_t so = sb + s * STAGEB;
        cp16(so + dA0, Ab + (size_t)ra0 * K + k0 + qa * 8);
        cp16(so + dA1, Ab + (size_t)(ra0 + 64) * K + k0 + qa * 8);
        #pragma unroll
        for (int j = 0; j < 4; j++) {
            int idx = tid + j * 256;
            int rb = idx >> 2, qb = idx & 3;
            cp16(so + ASZ_A + rb * ROWB + qb * 16,
                 Bb + (size_t)rb * K + k0 + qb * 8);
        }
        CP_COMMIT();
    }

    int la_r = (lane & 7) + ((lane >> 3) & 1) * 8;
    int la_c = ((lane >> 4) & 1) * 16;
    int lb_r = (lane & 7) + ((lane >> 4) & 1) * 8;
    int lb_c = ((lane >> 3) & 1) * 16;

    for (int c = 0; c < nch; c++) {
        if (c + NSTAGE - 1 < nch) { CP_WAIT(2); } else { CP_WAIT(0); }
        __syncthreads();

        if (c + NSTAGE - 1 < nch) {
            int s = (c + NSTAGE - 1) & (NSTAGE - 1);
            int k0 = (c + NSTAGE - 1) << 5;
            uint32_t so = sb + s * STAGEB;
            cp16(so + dA0, Ab + (size_t)ra0 * K + k0 + qa * 8);
            cp16(so + dA1, Ab + (size_t)(ra0 + 64) * K + k0 + qa * 8);
            #pragma unroll
            for (int j = 0; j < 4; j++) {
                int idx = tid + j * 256;
                int rb = idx >> 2, qb = idx & 3;
                cp16(so + ASZ_A + rb * ROWB + qb * 16,
                     Bb + (size_t)rb * K + k0 + qb * 8);
            }
            CP_COMMIT();
        }

        uint32_t sA = sb + (c & (NSTAGE - 1)) * STAGEB;
        uint32_t sB = sA + ASZ_A;

        #pragma unroll
        for (int ks = 0; ks < 2; ks++) {
            int kb = ks * 32;
            uint32_t af[4][4];
            uint32_t bf[8][2];
            #pragma unroll
            for (int f = 0; f < 4; f++) {
                uint32_t addr = sA + (wm + f * 16 + la_r) * ROWB + kb + la_c;
                ldsm4(af[f][0], af[f][1], af[f][2], af[f][3], addr);
            }
            #pragma unroll
            for (int np = 0; np < 4; np++) {
                uint32_t addr = sB + (wn + np * 16 + lb_r) * ROWB + kb + lb_c;
                ldsm4(bf[2 * np][0], bf[2 * np][1],
                      bf[2 * np + 1][0], bf[2 * np + 1][1], addr);
            }
            #pragma unroll
            for (int f = 0; f < 4; f++)
                #pragma unroll
                for (int n = 0; n < 8; n++)
                    mma_f16(acc[f][n], af[f], bf[n]);
        }
        // NOTE: no trailing sync — the top-of-loop barrier orders buffer reuse.
    }

    // ---- epilogue ----
    #pragma unroll
    for (int f = 0; f < 4; f++) {
        int rr = m0 + wm + f * 16 + g;
        #pragma unroll
        for (int n = 0; n < 8; n++) {
            int gc = n0 + wn + n * 8 + 2 * t;
            float v0 = acc[f][n][0], v1 = acc[f][n][1];
            float v2 = acc[f][n][2], v3 = acc[f][n][3];
            if (EPI == 5) {
                if (n0 >= 3 * DMODEL) {
                    int cc = gc - 3 * DMODEL;
                    float* G = (float*)aux;
                    G[(size_t)rr * DMODEL + cc]           = sigmoid_f(v0);
                    G[(size_t)rr * DMODEL + cc + 1]       = sigmoid_f(v1);
                    G[(size_t)(rr + 8) * DMODEL + cc]     = sigmoid_f(v2);
                    G[(size_t)(rr + 8) * DMODEL + cc + 1] = sigmoid_f(v3);
                } else {
                    __half* Q = (__half*)Cv;
                    *(__half2*)(Q + (size_t)rr * (3 * DMODEL) + gc)       = __floats2half2_rn(v0, v1);
                    *(__half2*)(Q + (size_t)(rr + 8) * (3 * DMODEL) + gc) = __floats2half2_rn(v2, v3);
                }
            } else if (EPI == 6) {
                // interleaved FFN: even B-row = g, odd = u; out col = pair idx
                int j = ((n0 + wn + n * 8) >> 1) + t;
                __half* C = (__half*)Cv;
                C[(size_t)rr * DFF + j]       = __float2half(v0 * sigmoid_f(v0) * v1);
                C[(size_t)(rr + 8) * DFF + j] = __float2half(v2 * sigmoid_f(v2) * v3);
            } else {  // EPI == 4
                size_t i0 = (size_t)rr * N + gc;
                size_t i1 = (size_t)(rr + 8) * N + gc;
                float2 x0 = *(const float2*)(aux + i0);
                float2 x1 = *(const float2*)(aux + i1);
                float* C = (float*)Cv;
                *(float2*)(C + i0) = make_float2(v0 + x0.x, v1 + x0.y);
                *(float2*)(C + i1) = make_float2(v2 + x1.x, v3 + x1.y);
            }
        }
    }
}

// ---------------------------------------------------------------------------
// Tensor-core flash attention, sliding window, fused gate. fp16 qkv input,
// cp.async staging (no conversion). 4 warps, 64 q-rows per block.
// smem row stride 72 halfs (144B) -> conflict-free ldmatrix & cp.async.
// ---------------------------------------------------------------------------
__global__ void __launch_bounds__(128) attn_mma_kernel(
    const __half* __restrict__ qkv, const float* __restrict__ gate,
    __half* __restrict__ out)
{
    __shared__ __align__(16) __half Qs[64 * 72];
    __shared__ __align__(16) __half Ks[64 * 72];
    __shared__ __align__(16) __half Vs[64 * 72];

    int tid = threadIdx.x;
    int warp = tid >> 5, lane = tid & 31;
    int g = lane >> 2, t = lane & 3;
    int b = blockIdx.y >> 4, h = blockIdx.y & 15;
    int q0 = blockIdx.x * 64;
    int wm16 = warp * 16;

    uint32_t qbase = smem_u32(Qs);
    uint32_t kbase = smem_u32(Ks);
    uint32_t vbase = smem_u32(Vs);

    // stage Q tile [64 x 64] via cp.async (rows of 128B = 8 x 16B)
    {
        int r = tid >> 1;           // 0..63
        int c = (tid & 1) * 4;      // 0 or 4 -> chunks c..c+3
        const __half* src = qkv + ((size_t)(b * TSEQ + q0 + r)) * (3 * DMODEL) + h * DHEAD + c * 8;
        uint32_t dst = qbase + r * 144 + c * 16;
        #pragma unroll
        for (int j = 0; j < 4; j++) cp16(dst + j * 16, src + j * 8);
        CP_COMMIT();
    }

    int la_r = (lane & 7) + ((lane >> 3) & 1) * 8;
    int la_c = ((lane >> 4) & 1) * 8;
    int lb_r = (lane & 7) + ((lane >> 4) & 1) * 8;
    int lb_c = ((lane >> 3) & 1) * 8;

    CP_WAIT(0);
    __syncthreads();

    uint32_t qf[4][4];
    #pragma unroll
    for (int ks = 0; ks < 4; ks++) {
        uint32_t addr = qbase + ((wm16 + la_r) * 72 + ks * 16 + la_c) * 2;
        ldsm4(qf[ks][0], qf[ks][1], qf[ks][2], qf[ks][3], addr);
    }

    float oacc[8][4];
    #pragma unroll
    for (int n = 0; n < 8; n++)
        #pragma unroll
        for (int i = 0; i < 4; i++) oacc[n][i] = 0.0f;
    float m0 = -1e30f, m1 = -1e30f, l0 = 0.0f, l1 = 0.0f;
    int qi0 = q0 + wm16 + g;
    int qi1 = qi0 + 8;

    int s_lo = q0 - WINDOW;
    if (s_lo < 0) s_lo = 0;

    for (int s = s_lo; s <= q0; s += 64) {
        __syncthreads();   // previous readers done before overwrite
        {
            int r = tid >> 1;
            int c = (tid & 1) * 4;
            size_t base = ((size_t)(b * TSEQ + s + r)) * (3 * DMODEL) + h * DHEAD + c * 8;
            uint32_t dK = kbase + r * 144 + c * 16;
            uint32_t dV = vbase + r * 144 + c * 16;
            #pragma unroll
            for (int j = 0; j < 4; j++) {
                cp16(dK + j * 16, qkv + base + DMODEL + j * 8);
                cp16(dV + j * 16, qkv + base + 2 * DMODEL + j * 8);
            }
            CP_COMMIT();
        }
        CP_WAIT(0);
        __syncthreads();

        // S = Q * K^T
        float sacc[8][4];
        #pragma unroll
        for (int n = 0; n < 8; n++)
            #pragma unroll
            for (int i = 0; i < 4; i++) sacc[n][i] = 0.0f;

        #pragma unroll
        for (int ks = 0; ks < 4; ks++) {
            uint32_t bf[8][2];
            #pragma unroll
            for (int np = 0; np < 4; np++) {
                uint32_t addr = kbase + ((np * 16 + lb_r) * 72 + ks * 16 + lb_c) * 2;
                ldsm4(bf[2 * np][0], bf[2 * np][1],
                      bf[2 * np + 1][0], bf[2 * np + 1][1], addr);
            }
            #pragma unroll
            for (int nf = 0; nf < 8; nf++)
                mma_f16(sacc[nf], qf[ks], bf[nf]);
        }

        // mask + scale + online softmax
        float mt0 = -1e30f, mt1 = -1e30f;
        #pragma unroll
        for (int nf = 0; nf < 8; nf++) {
            int key = s + nf * 8 + 2 * t;
            #pragma unroll
            for (int c = 0; c < 2; c++) {
                unsigned d0 = (unsigned)(qi0 - (key + c));
                unsigned d1 = (unsigned)(qi1 - (key + c));
                float v0 = (d0 < (unsigned)WINDOW) ? sacc[nf][c] * 0.125f : -1e30f;
                float v1 = (d1 < (unsigned)WINDOW) ? sacc[nf][c + 2] * 0.125f : -1e30f;
                sacc[nf][c] = v0; sacc[nf][c + 2] = v1;
                mt0 = fmaxf(mt0, v0); mt1 = fmaxf(mt1, v1);
            }
        }
        mt0 = fmaxf(mt0, __shfl_xor_sync(0xffffffffu, mt0, 1));
        mt0 = fmaxf(mt0, __shfl_xor_sync(0xffffffffu, mt0, 2));
        mt1 = fmaxf(mt1, __shfl_xor_sync(0xffffffffu, mt1, 1));
        mt1 = fmaxf(mt1, __shfl_xor_sync(0xffffffffu, mt1, 2));

        float mn0 = fmaxf(m0, mt0), mn1 = fmaxf(m1, mt1);
        float cor0 = __expf(m0 - mn0), cor1 = __expf(m1 - mn1);
        m0 = mn0; m1 = mn1;
        l0 *= cor0; l1 *= cor1;
        #pragma unroll
        for (int nf = 0; nf < 8; nf++) {
            oacc[nf][0] *= cor0; oacc[nf][1] *= cor0;
            oacc[nf][2] *= cor1; oacc[nf][3] *= cor1;
        }
        float ps0 = 0.0f, ps1 = 0.0f;
        #pragma unroll
        for (int nf = 0; nf < 8; nf++) {
            #pragma unroll
            for (int c = 0; c < 2; c++) {
                float p0 = __expf(sacc[nf][c] - m0);
                float p1 = __expf(sacc[nf][c + 2] - m1);
                sacc[nf][c] = p0; sacc[nf][c + 2] = p1;
                ps0 += p0; ps1 += p1;
            }
        }
        l0 += ps0; l1 += ps1;

        // O += P * V
        #pragma unroll
        for (int kc = 0; kc < 4; kc++) {
            uint32_t pf[4];
            pf[0] = packh2(sacc[2 * kc][0],     sacc[2 * kc][1]);
            pf[1] = packh2(sacc[2 * kc][2],     sacc[2 * kc][3]);
            pf[2] = packh2(sacc[2 * kc + 1][0], sacc[2 * kc + 1][1]);
            pf[3] = packh2(sacc[2 * kc + 1][2], sacc[2 * kc + 1][3]);
            #pragma unroll
            for (int dp = 0; dp < 4; dp++) {
                uint32_t addr = vbase + ((kc * 16 + la_r) * 72 + dp * 16 + la_c) * 2;
                uint32_t v0, v1, v2, v3;
                ldsm4t(v0, v1, v2, v3, addr);
                uint32_t bb0[2] = { v0, v1 };
                uint32_t bb1[2] = { v2, v3 };
                mma_f16(oacc[2 * dp], pf, bb0);
                mma_f16(oacc[2 * dp + 1], pf, bb1);
            }
        }
    }

    l0 += __shfl_xor_sync(0xffffffffu, l0, 1);
    l0 += __shfl_xor_sync(0xffffffffu, l0, 2);
    l1 += __shfl_xor_sync(0xffffffffu, l1, 1);
    l1 += __shfl_xor_sync(0xffffffffu, l1, 2);
    float inv0 = 1.0f / l0, inv1 = 1.0f / l1;

    size_t tq0 = (size_t)b * TSEQ + qi0;
    size_t tq1 = tq0 + 8;
    #pragma unroll
    for (int nf = 0; nf < 8; nf++) {
        int col = h * DHEAD + nf * 8 + 2 * t;
        float2 g0 = *(const float2*)(gate + tq0 * DMODEL + col);
        float2 g1 = *(const float2*)(gate + tq1 * DMODEL + col);
        *(__half2*)(out + tq0 * DMODEL + col) =
            __floats2half2_rn(oacc[nf][0] * inv0 * g0.x, oacc[nf][1] * inv0 * g0.y);
        *(__half2*)(out + tq1 * DMODEL + col) =
            __floats2half2_rn(oacc[nf][2] * inv1 * g1.x, oacc[nf][3] * inv1 * g1.y);
    }
}

// ---------------------------------------------------------------------------
// Launch
// ---------------------------------------------------------------------------
extern "C" void kernel_launch(void* const* d_in, const int* in_sizes, int n_in,
                              void* d_out, int out_size)
{
    const float* x      = (const float*)d_in[0];
    const float* ln1_w  = (const float*)d_in[1];
    const float* qkv_w  = (const float*)d_in[2];
    const float* gate_w = (const float*)d_in[3];
    const float* out_w  = (const float*)d_in[4];
    const float* ln2_w  = (const float*)d_in[5];
    const float* wg     = (const float*)d_in[6];
    const float* wu     = (const float*)d_in[7];
    const float* wo     = (const float*)d_in[8];
    float* out = (float*)d_out;

    float *gateb;
    __half *xnh, *qkvh, *attnh, *hnh, *ubh, *wqg, *wouth, *wfh, *woh;
    cudaGetSymbolAddress((void**)&xnh,   g_xn_h);
    cudaGetSymbolAddress((void**)&qkvh,  g_qkv_h);
    cudaGetSymbolAddress((void**)&gateb, g_gate);
    cudaGetSymbolAddress((void**)&attnh, g_attn_h);
    cudaGetSymbolAddress((void**)&hnh,   g_hn_h);
    cudaGetSymbolAddress((void**)&ubh,   g_u_h);
    cudaGetSymbolAddress((void**)&wqg,   g_wqg);
    cudaGetSymbolAddress((void**)&wouth, g_wout);
    cudaGetSymbolAddress((void**)&wfh,   g_wf);
    cudaGetSymbolAddress((void**)&woh,   g_wo);

    cudaFuncSetAttribute(gemm_h<4>, cudaFuncAttributeMaxDynamicSharedMemorySize, GSMEM);
    cudaFuncSetAttribute(gemm_h<5>, cudaFuncAttributeMaxDynamicSharedMemorySize, GSMEM);
    cudaFuncSetAttribute(gemm_h<6>, cudaFuncAttributeMaxDynamicSharedMemorySize, GSMEM);

    // 0. all weights -> fp16 (one launch; wg/wu row-interleaved)
    w2h_all<<<W2H_TOT / 256, 256>>>(qkv_w, gate_w, out_w, wg, wu, wo,
                                    wqg, wouth, wfh, woh);

    // 1. xn = rmsnorm(x, ln1_w) -> fp16
    rmsnorm_kernel<<<TOKENS, 256>>>(x, ln1_w, xnh);

    // 2+3. fused qkv|gate GEMM: qkv -> fp16, gate -> sigmoid fp32
    gemm_h<5><<<dim3(4 * DMODEL / 256, TOKENS / 128), 256, GSMEM>>>(
        xnh, wqg, qkvh, gateb, TOKENS, 4 * DMODEL, DMODEL);

    // 4. attn (tensor-core flash) -> fp16
    attn_mma_kernel<<<dim3(TSEQ / 64, 2 * NHEADS), 128>>>(qkvh, gateb, attnh);

    // 5. x1 = x + attn @ out_w^T -> d_out (fp32)
    gemm_h<4><<<dim3(DMODEL / 256, TOKENS / 128), 256, GSMEM>>>(
        attnh, wouth, out, x, TOKENS, DMODEL, DMODEL);

    // 6. hn = rmsnorm(x1, ln2_w) -> fp16
    rmsnorm_kernel<<<TOKENS, 256>>>(out, ln2_w, hnh);

    // 7+8. fused FFN: ub = silu(hn@wg^T) * (hn@wu^T) -> fp16 (interleaved B)
    gemm_h<6><<<dim3(2 * DFF / 256, TOKENS / 128), 256, GSMEM>>>(
        hnh, wfh, ubh, nullptr, TOKENS, 2 * DFF, DMODEL);

    // 9. out = x1 + ub @ wo^T (in-place residual on d_out)
    gemm_h<4><<<dim3(DMODEL / 256, TOKENS / 128), 256, GSMEM>>>(
        ubh, woh, out, out, TOKENS, DMODEL, DFF);
}